// round 7
// baseline (speedup 1.0000x reference)
#include <cuda_runtime.h>

// ---------------------------------------------------------------------------
// dims
// ---------------------------------------------------------------------------
#define BB   16
#define TT   120
#define NJ   24
#define DIM  256
#define NH   8
#define DPH  32
#define BT   (BB * TT)        // 1920
#define ROWS (BT * NJ)        // 46080
#define NELEM (ROWS * DIM)    // 11,796,480

// ---------------------------------------------------------------------------
// scratch buffers (device globals: allocation-free per harness rules)
// ---------------------------------------------------------------------------
__device__ float g_q[NELEM];
__device__ float g_k[NELEM];
__device__ float g_v[NELEM];
__device__ float g_ao[NELEM];
__device__ float g_y[NELEM];
__device__ float g_h[NELEM];

// ---------------------------------------------------------------------------
// Generic tiled SGEMM:  Out[m][n] = sum_k X[m][k] * W[k][n] + bias[n]
//                               (+ addsrc[m][n]) (+ ReLU)
// 64x64 block tile, 4x4 per-thread microtile, K-chunks of 16.
// blockIdx.z = batch (joint) index; per-batch offsets zoff_x (applied to X,
// Out, addsrc: offset *within* the row layout), zoff_w, zoff_b.
// row_stride is the element stride between consecutive M-rows of X/Out/addsrc.
// ---------------------------------------------------------------------------
__global__ void __launch_bounds__(256) gemm64(
    const float* __restrict__ X, const float* __restrict__ W,
    const float* __restrict__ Bv, const float* __restrict__ Rsrc,
    float* __restrict__ Out,
    int row_stride, int zoff_x, int zoff_w, int zoff_b, int relu)
{
    __shared__ __align__(16) float As[64][17];
    __shared__ __align__(16) float Bs[16][64];

    const int z = blockIdx.z;
    const float* Xb = X + (size_t)z * zoff_x;
    const float* Wb = W + (size_t)z * zoff_w;
    const float* Bb = Bv + (size_t)z * zoff_b;
    float*       Ob = Out + (size_t)z * zoff_x;
    const float* Rb = Rsrc ? (Rsrc + (size_t)z * zoff_x) : nullptr;

    const int m0 = blockIdx.x * 64;
    const int n0 = blockIdx.y * 64;
    const int tid = threadIdx.x;
    const int tx4 = (tid & 15) * 4;
    const int ty4 = (tid >> 4) * 4;

    float acc[4][4];
#pragma unroll
    for (int i = 0; i < 4; i++)
#pragma unroll
        for (int j = 0; j < 4; j++) acc[i][j] = 0.f;

    const int lk  = tid & 15;   // k within chunk (A load)
    const int lm  = tid >> 4;   // m base        (A load)
    const int ln  = tid & 63;   // n             (B load)
    const int lkb = tid >> 6;   // k base        (B load)

    for (int kc = 0; kc < DIM; kc += 16) {
#pragma unroll
        for (int i = 0; i < 4; i++)
            As[lm + i * 16][lk] =
                Xb[(size_t)(m0 + lm + i * 16) * row_stride + kc + lk];
#pragma unroll
        for (int i = 0; i < 4; i++)
            Bs[lkb + i * 4][ln] =
                Wb[(size_t)(kc + lkb + i * 4) * DIM + n0 + ln];
        __syncthreads();

#pragma unroll
        for (int k = 0; k < 16; k++) {
            const float a0 = As[ty4 + 0][k];
            const float a1 = As[ty4 + 1][k];
            const float a2 = As[ty4 + 2][k];
            const float a3 = As[ty4 + 3][k];
            const float4 b = *reinterpret_cast<const float4*>(&Bs[k][tx4]);
            acc[0][0] = fmaf(a0, b.x, acc[0][0]);
            acc[0][1] = fmaf(a0, b.y, acc[0][1]);
            acc[0][2] = fmaf(a0, b.z, acc[0][2]);
            acc[0][3] = fmaf(a0, b.w, acc[0][3]);
            acc[1][0] = fmaf(a1, b.x, acc[1][0]);
            acc[1][1] = fmaf(a1, b.y, acc[1][1]);
            acc[1][2] = fmaf(a1, b.z, acc[1][2]);
            acc[1][3] = fmaf(a1, b.w, acc[1][3]);
            acc[2][0] = fmaf(a2, b.x, acc[2][0]);
            acc[2][1] = fmaf(a2, b.y, acc[2][1]);
            acc[2][2] = fmaf(a2, b.z, acc[2][2]);
            acc[2][3] = fmaf(a2, b.w, acc[2][3]);
            acc[3][0] = fmaf(a3, b.x, acc[3][0]);
            acc[3][1] = fmaf(a3, b.y, acc[3][1]);
            acc[3][2] = fmaf(a3, b.z, acc[3][2]);
            acc[3][3] = fmaf(a3, b.w, acc[3][3]);
        }
        __syncthreads();
    }

    const float4 bias4 = *reinterpret_cast<const float4*>(&Bb[n0 + tx4]);
#pragma unroll
    for (int i = 0; i < 4; i++) {
        const size_t off = (size_t)(m0 + ty4 + i) * row_stride + n0 + tx4;
        float4 r;
        r.x = acc[i][0] + bias4.x;
        r.y = acc[i][1] + bias4.y;
        r.z = acc[i][2] + bias4.z;
        r.w = acc[i][3] + bias4.w;
        if (Rb) {
            const float4 a = *reinterpret_cast<const float4*>(Rb + off);
            r.x += a.x; r.y += a.y; r.z += a.z; r.w += a.w;
        }
        if (relu) {
            r.x = fmaxf(r.x, 0.f);
            r.y = fmaxf(r.y, 0.f);
            r.z = fmaxf(r.z, 0.f);
            r.w = fmaxf(r.w, 0.f);
        }
        *reinterpret_cast<float4*>(Ob + off) = r;
    }
}

// ---------------------------------------------------------------------------
// Temporal attention: one block per (h, n, b). Causal, with relative-position
// key/value tables. Only rel indices 0..32 are reachable under causality.
// smem floats: q/k/v/R 4*3960 + rk/rv 2*1056 + A0 120 + S 14400 = 32472
// ---------------------------------------------------------------------------
#define TATTN_SMEM (32472 * 4)

__global__ void __launch_bounds__(256) tattn(
    const float* __restrict__ Q, const float* __restrict__ K,
    const float* __restrict__ V,
    const float* __restrict__ relk, const float* __restrict__ relv,
    float* __restrict__ O)
{
    extern __shared__ float sm[];
    float* sq  = sm;           // [120][33]
    float* sk  = sq + 3960;    // [120][33]
    float* sv  = sk + 3960;    // [120][33]
    float* sR  = sv + 3960;    // [120][33]  R[t][j] = q[t].relk[j]
    float* srk = sR + 3960;    // [33][32]
    float* srv = srk + 1056;   // [33][32]
    float* sA0 = srv + 1056;   // [120]
    float* sS  = sA0 + 120;    // [120][120]

    const int h = blockIdx.x, n = blockIdx.y, b = blockIdx.z;
    const int tid = threadIdx.x;
    const size_t base = ((size_t)(b * TT) * NJ + n) * DIM + h * DPH;

    // load q,k,v rows (coalesced 128B per row) and rel tables
    for (int i = tid; i < TT * DPH; i += 256) {
        const int t = i >> 5, d = i & 31;
        const size_t g = base + (size_t)t * (NJ * DIM) + d;
        sq[t * 33 + d] = Q[g];
        sk[t * 33 + d] = K[g];
        sv[t * 33 + d] = V[g];
    }
    for (int i = tid; i < 33 * 32; i += 256) {
        srk[i] = relk[i];   // rows 0..32 of the [65][32] table are contiguous
        srv[i] = relv[i];
    }
    __syncthreads();

    // R[t][j] = q[t] . relk[j]
    for (int p = tid; p < TT * 33; p += 256) {
        const int t = p / 33, j = p % 33;
        const float* qa = sq + t * 33;
        const float* ra = srk + j * 32;
        float s = 0.f;
#pragma unroll
        for (int d = 0; d < 32; d++) s = fmaf(qa[d], ra[d], s);
        sR[p] = s;
    }
    __syncthreads();

    // S[t][s] = (q[t].k[s] + R[t][clip(s-t)+32]) * scale  (4x4 tiles, skip
    // fully-masked tiles; masked entries get zeroed in the softmax pass)
    const float scale = 0.17677669529663687f;  // 1/sqrt(32)
    for (int p = tid; p < 900; p += 256) {
        const int tt = (p / 30) * 4, ss = (p % 30) * 4;
        if (ss > tt + 3) continue;  // entire tile above the diagonal
        float c[4][4];
#pragma unroll
        for (int i = 0; i < 4; i++)
#pragma unroll
            for (int j = 0; j < 4; j++) c[i][j] = 0.f;
#pragma unroll
        for (int d = 0; d < 32; d++) {
            const float a0 = sq[(tt + 0) * 33 + d];
            const float a1 = sq[(tt + 1) * 33 + d];
            const float a2 = sq[(tt + 2) * 33 + d];
            const float a3 = sq[(tt + 3) * 33 + d];
            const float b0 = sk[(ss + 0) * 33 + d];
            const float b1 = sk[(ss + 1) * 33 + d];
            const float b2 = sk[(ss + 2) * 33 + d];
            const float b3 = sk[(ss + 3) * 33 + d];
            c[0][0] = fmaf(a0, b0, c[0][0]); c[0][1] = fmaf(a0, b1, c[0][1]);
            c[0][2] = fmaf(a0, b2, c[0][2]); c[0][3] = fmaf(a0, b3, c[0][3]);
            c[1][0] = fmaf(a1, b0, c[1][0]); c[1][1] = fmaf(a1, b1, c[1][1]);
            c[1][2] = fmaf(a1, b2, c[1][2]); c[1][3] = fmaf(a1, b3, c[1][3]);
            c[2][0] = fmaf(a2, b0, c[2][0]); c[2][1] = fmaf(a2, b1, c[2][1]);
            c[2][2] = fmaf(a2, b2, c[2][2]); c[2][3] = fmaf(a2, b3, c[2][3]);
            c[3][0] = fmaf(a3, b0, c[3][0]); c[3][1] = fmaf(a3, b1, c[3][1]);
            c[3][2] = fmaf(a3, b2, c[3][2]); c[3][3] = fmaf(a3, b3, c[3][3]);
        }
#pragma unroll
        for (int i = 0; i < 4; i++) {
#pragma unroll
            for (int j = 0; j < 4; j++) {
                const int t = tt + i, s = ss + j;
                int idx = s - t + 32;
                idx = idx < 0 ? 0 : (idx > 32 ? 32 : idx);
                sS[t * 120 + s] = (c[i][j] + sR[t * 33 + idx]) * scale;
            }
        }
    }
    __syncthreads();

    // softmax per row (causal), + zero masked entries, + A0 bucket sums
    {
        const int wid = tid >> 5, lane = tid & 31;
        for (int t = wid; t < TT; t += 8) {
            float* row = sS + t * 120;
            float m = -1e30f;
            for (int s = lane; s <= t; s += 32) m = fmaxf(m, row[s]);
#pragma unroll
            for (int o = 16; o > 0; o >>= 1)
                m = fmaxf(m, __shfl_xor_sync(0xffffffffu, m, o));
            float sum = 0.f;
            for (int s = lane; s <= t; s += 32) {
                const float e = __expf(row[s] - m);
                row[s] = e;
                sum += e;
            }
#pragma unroll
            for (int o = 16; o > 0; o >>= 1)
                sum += __shfl_xor_sync(0xffffffffu, sum, o);
            const float inv = 1.f / sum;
            float a0 = 0.f;
            for (int s = lane; s <= t; s += 32) {
                const float a = row[s] * inv;
                row[s] = a;
                if (s <= t - 32) a0 += a;  // clipped bucket (idx == 0)
            }
#pragma unroll
            for (int o = 16; o > 0; o >>= 1)
                a0 += __shfl_xor_sync(0xffffffffu, a0, o);
            if (lane == 0) sA0[t] = a0;
            for (int s = t + 1 + lane; s < 120; s += 32) row[s] = 0.f;
        }
    }
    __syncthreads();

    // out[t][d] = sum_s a[t][s]*v[s][d]
    //           + A0[t]*rv[0][d] + sum_{idx in [1,32]} a[t][s]*rv[idx][d]
    for (int p = tid; p < 240; p += 256) {
        const int tt = (p / 8) * 4, dd = (p % 8) * 4;
        float c[4][4];
#pragma unroll
        for (int i = 0; i < 4; i++)
#pragma unroll
            for (int j = 0; j < 4; j++) c[i][j] = 0.f;

        const int smax = tt + 3;  // tt <= 116 so smax <= 119
        for (int s = 0; s <= smax; s++) {
            const float a0s = sS[(tt + 0) * 120 + s];
            const float a1s = sS[(tt + 1) * 120 + s];
            const float a2s = sS[(tt + 2) * 120 + s];
            const float a3s = sS[(tt + 3) * 120 + s];
            const float v0 = sv[s * 33 + dd + 0];
            const float v1 = sv[s * 33 + dd + 1];
            const float v2 = sv[s * 33 + dd + 2];
            const float v3 = sv[s * 33 + dd + 3];
            c[0][0] = fmaf(a0s, v0, c[0][0]); c[0][1] = fmaf(a0s, v1, c[0][1]);
            c[0][2] = fmaf(a0s, v2, c[0][2]); c[0][3] = fmaf(a0s, v3, c[0][3]);
            c[1][0] = fmaf(a1s, v0, c[1][0]); c[1][1] = fmaf(a1s, v1, c[1][1]);
            c[1][2] = fmaf(a1s, v2, c[1][2]); c[1][3] = fmaf(a1s, v3, c[1][3]);
            c[2][0] = fmaf(a2s, v0, c[2][0]); c[2][1] = fmaf(a2s, v1, c[2][1]);
            c[2][2] = fmaf(a2s, v2, c[2][2]); c[2][3] = fmaf(a2s, v3, c[2][3]);
            c[3][0] = fmaf(a3s, v0, c[3][0]); c[3][1] = fmaf(a3s, v1, c[3][1]);
            c[3][2] = fmaf(a3s, v2, c[3][2]); c[3][3] = fmaf(a3s, v3, c[3][3]);
        }

        // clipped bucket (all s <= t-32 mapped to rel index 0)
#pragma unroll
        for (int i = 0; i < 4; i++) {
            const float a0v = sA0[tt + i];
            c[i][0] = fmaf(a0v, srv[dd + 0], c[i][0]);
            c[i][1] = fmaf(a0v, srv[dd + 1], c[i][1]);
            c[i][2] = fmaf(a0v, srv[dd + 2], c[i][2]);
            c[i][3] = fmaf(a0v, srv[dd + 3], c[i][3]);
        }
        // rel indices 1..32 (last <=32 positions per row)
        const int slo = (tt - 31) > 0 ? (tt - 31) : 0;
        for (int s = slo; s <= smax; s++) {
#pragma unroll
            for (int i = 0; i < 4; i++) {
                const int idx = s - (tt + i) + 32;
                if (idx >= 1 && idx <= 32) {
                    const float a = sS[(tt + i) * 120 + s];
                    const float* rp = srv + idx * 32 + dd;
                    c[i][0] = fmaf(a, rp[0], c[i][0]);
                    c[i][1] = fmaf(a, rp[1], c[i][1]);
                    c[i][2] = fmaf(a, rp[2], c[i][2]);
                    c[i][3] = fmaf(a, rp[3], c[i][3]);
                }
            }
        }

#pragma unroll
        for (int i = 0; i < 4; i++) {
            const size_t g = base + (size_t)(tt + i) * (NJ * DIM) + dd;
            O[g + 0] = c[i][0];
            O[g + 1] = c[i][1];
            O[g + 2] = c[i][2];
            O[g + 3] = c[i][3];
        }
    }
}

// ---------------------------------------------------------------------------
// Spatial attention: one block per (b,t); all 8 heads over N=24 joints.
// smem floats: 3*6144 + 4608 = 23040
// ---------------------------------------------------------------------------
#define SATTN_SMEM (23040 * 4)

__global__ void __launch_bounds__(256) sattn(
    const float* __restrict__ Q, const float* __restrict__ K,
    const float* __restrict__ V, float* __restrict__ O)
{
    extern __shared__ float sm[];
    float* sq = sm;            // [24][256]
    float* sk = sq + 6144;
    float* sv = sk + 6144;
    float* sS = sv + 6144;     // [8][24][24]

    const int tid = threadIdx.x;
    const size_t base = (size_t)blockIdx.x * (NJ * DIM);

    for (int i = tid; i < NJ * DIM; i += 256) {
        sq[i] = Q[base + i];
        sk[i] = K[base + i];
        sv[i] = V[base + i];
    }
    __syncthreads();

    const float scale = 0.17677669529663687f;
    for (int p = tid; p < NH * NJ * NJ; p += 256) {
        const int hh = p / (NJ * NJ);
        const int r = p % (NJ * NJ);
        const int i = r / NJ, j = r % NJ;
        const float* qa = sq + i * DIM + hh * DPH;
        const float* ka = sk + j * DIM + hh * DPH;
        float s = 0.f;
#pragma unroll
        for (int d = 0; d < 32; d++) s = fmaf(qa[d], ka[d], s);
        sS[p] = s * scale;
    }
    __syncthreads();

    // softmax: 192 rows of 24, one thread per row
    for (int r = tid; r < NH * NJ; r += 256) {
        float* row = sS + r * NJ;
        float m = -1e30f;
#pragma unroll
        for (int j = 0; j < NJ; j++) m = fmaxf(m, row[j]);
        float sum = 0.f;
#pragma unroll
        for (int j = 0; j < NJ; j++) {
            const float e = __expf(row[j] - m);
            row[j] = e;
            sum += e;
        }
        const float inv = 1.f / sum;
#pragma unroll
        for (int j = 0; j < NJ; j++) row[j] *= inv;
    }
    __syncthreads();

    for (int p = tid; p < NJ * DIM; p += 256) {
        const int hh = p / (NJ * DPH);
        const int r = p % (NJ * DPH);
        const int i = r / DPH, d = r % DPH;
        const float* arow = sS + hh * (NJ * NJ) + i * NJ;
        const float* vcol = sv + hh * DPH + d;
        float s = 0.f;
#pragma unroll
        for (int j = 0; j < NJ; j++) s = fmaf(arow[j], vcol[j * DIM], s);
        O[base + (size_t)i * DIM + hh * DPH + d] = s;
    }
}

// ---------------------------------------------------------------------------
// launch
// ---------------------------------------------------------------------------
extern "C" void kernel_launch(void* const* d_in, const int* in_sizes, int n_in,
                              void* d_out, int out_size)
{
    (void)in_sizes; (void)n_in; (void)out_size;
    const float* x    = (const float*)d_in[0];
    // d_in[1] = mask: exactly triu(1) -> handled analytically (exp underflow)
    const float* wq_t = (const float*)d_in[2];
    const float* wk_t = (const float*)d_in[3];
    const float* wv_t = (const float*)d_in[4];
    const float* bq_t = (const float*)d_in[5];
    const float* bk_t = (const float*)d_in[6];
    const float* bv_t = (const float*)d_in[7];
    const float* wo_t = (const float*)d_in[8];
    const float* bo_t = (const float*)d_in[9];
    const float* relk = (const float*)d_in[10];
    const float* relv = (const float*)d_in[11];
    const float* wq_s = (const float*)d_in[12];
    const float* wk_s = (const float*)d_in[13];
    const float* wv_s = (const float*)d_in[14];
    const float* wo_s = (const float*)d_in[15];
    const float* bq_s = (const float*)d_in[16];
    const float* bk_s = (const float*)d_in[17];
    const float* bv_s = (const float*)d_in[18];
    const float* bo_s = (const float*)d_in[19];
    const float* ff1w = (const float*)d_in[20];
    const float* ff1b = (const float*)d_in[21];
    const float* ff2w = (const float*)d_in[22];
    const float* ff2b = (const float*)d_in[23];
    float* out = (float*)d_out;

    float *dq, *dk, *dv, *dao, *dy, *dh;
    cudaGetSymbolAddress((void**)&dq, g_q);
    cudaGetSymbolAddress((void**)&dk, g_k);
    cudaGetSymbolAddress((void**)&dv, g_v);
    cudaGetSymbolAddress((void**)&dao, g_ao);
    cudaGetSymbolAddress((void**)&dy, g_y);
    cudaGetSymbolAddress((void**)&dh, g_h);

    cudaFuncSetAttribute(tattn, cudaFuncAttributeMaxDynamicSharedMemorySize,
                         TATTN_SMEM);
    cudaFuncSetAttribute(sattn, cudaFuncAttributeMaxDynamicSharedMemorySize,
                         SATTN_SMEM);

    const dim3 gj(BT / 64, DIM / 64, NJ);    // per-joint GEMMs (M=1920 each)
    const dim3 gs(ROWS / 64, DIM / 64, 1);   // shared-weight GEMMs (M=46080)

    // ---- temporal attention path ----
    gemm64<<<gj, 256>>>(x, wq_t, bq_t, nullptr, dq, NJ * DIM, DIM, DIM * DIM, DIM, 0);
    gemm64<<<gj, 256>>>(x, wk_t, bk_t, nullptr, dk, NJ * DIM, DIM, DIM * DIM, DIM, 0);
    gemm64<<<gj, 256>>>(x, wv_t, bv_t, nullptr, dv, NJ * DIM, DIM, DIM * DIM, DIM, 0);
    tattn<<<dim3(NH, NJ, BB), 256, TATTN_SMEM>>>(dq, dk, dv, relk, relv, dao);
    // y = x + t_out
    gemm64<<<gs, 256>>>(dao, wo_t, bo_t, x, dy, DIM, 0, 0, 0, 0);

    // ---- spatial attention path (input is x, not y) ----
    gemm64<<<gs, 256>>>(x, wq_s, bq_s, nullptr, dq, DIM, 0, 0, 0, 0);
    gemm64<<<gs, 256>>>(x, wk_s, bk_s, nullptr, dk, DIM, 0, 0, 0, 0);
    gemm64<<<gs, 256>>>(x, wv_s, bv_s, nullptr, dv, DIM, 0, 0, 0, 0);
    sattn<<<BT, 256, SATTN_SMEM>>>(dq, dk, dv, dao);
    // y += s_out
    gemm64<<<gs, 256>>>(dao, wo_s, bo_s, dy, dy, DIM, 0, 0, 0, 0);

    // ---- per-joint FFN + residual ----
    gemm64<<<gj, 256>>>(dy, ff1w, ff1b, nullptr, dh, NJ * DIM, DIM, DIM * DIM, DIM, 1);
    gemm64<<<gj, 256>>>(dh, ff2w, ff2b, dy, out, NJ * DIM, DIM, DIM * DIM, DIM, 0);
}

// round 8
// speedup vs baseline: 1.0033x; 1.0033x over previous
#include <cuda_runtime.h>

// ---------------------------------------------------------------------------
// dims
// ---------------------------------------------------------------------------
#define BB   16
#define TT   120
#define NJ   24
#define DIM  256
#define NH   8
#define DPH  32
#define BT   (BB * TT)        // 1920
#define ROWS (BT * NJ)        // 46080
#define NELEM (ROWS * DIM)    // 11,796,480

// ---------------------------------------------------------------------------
// scratch buffers (device globals: allocation-free per harness rules)
// ---------------------------------------------------------------------------
__device__ float g_q[NELEM];
__device__ float g_k[NELEM];
__device__ float g_v[NELEM];
__device__ float g_ao[NELEM];
__device__ float g_y[NELEM];
__device__ float g_h[NELEM];

// ---------------------------------------------------------------------------
// Generic tiled SGEMM:  Out[m][n] = sum_k X[m][k] * W[k][n] + bias[n]
//                               (+ addsrc[m][n]) (+ ReLU)
// 64x64 block tile, 4x4 per-thread microtile, K-chunks of 16.
// blockIdx.z = batch (joint) index; per-batch offsets zoff_x (applied to X,
// Out, addsrc: offset *within* the row layout), zoff_w, zoff_b.
// row_stride is the element stride between consecutive M-rows of X/Out/addsrc.
// ---------------------------------------------------------------------------
__global__ void __launch_bounds__(256) gemm64(
    const float* __restrict__ X, const float* __restrict__ W,
    const float* __restrict__ Bv, const float* __restrict__ Rsrc,
    float* __restrict__ Out,
    int row_stride, int zoff_x, int zoff_w, int zoff_b, int relu)
{
    __shared__ __align__(16) float As[64][17];
    __shared__ __align__(16) float Bs[16][64];

    const int z = blockIdx.z;
    const float* Xb = X + (size_t)z * zoff_x;
    const float* Wb = W + (size_t)z * zoff_w;
    const float* Bb = Bv + (size_t)z * zoff_b;
    float*       Ob = Out + (size_t)z * zoff_x;
    const float* Rb = Rsrc ? (Rsrc + (size_t)z * zoff_x) : nullptr;

    const int m0 = blockIdx.x * 64;
    const int n0 = blockIdx.y * 64;
    const int tid = threadIdx.x;
    const int tx4 = (tid & 15) * 4;
    const int ty4 = (tid >> 4) * 4;

    float acc[4][4];
#pragma unroll
    for (int i = 0; i < 4; i++)
#pragma unroll
        for (int j = 0; j < 4; j++) acc[i][j] = 0.f;

    const int lk  = tid & 15;   // k within chunk (A load)
    const int lm  = tid >> 4;   // m base        (A load)
    const int ln  = tid & 63;   // n             (B load)
    const int lkb = tid >> 6;   // k base        (B load)

    for (int kc = 0; kc < DIM; kc += 16) {
#pragma unroll
        for (int i = 0; i < 4; i++)
            As[lm + i * 16][lk] =
                Xb[(size_t)(m0 + lm + i * 16) * row_stride + kc + lk];
#pragma unroll
        for (int i = 0; i < 4; i++)
            Bs[lkb + i * 4][ln] =
                Wb[(size_t)(kc + lkb + i * 4) * DIM + n0 + ln];
        __syncthreads();

#pragma unroll
        for (int k = 0; k < 16; k++) {
            const float a0 = As[ty4 + 0][k];
            const float a1 = As[ty4 + 1][k];
            const float a2 = As[ty4 + 2][k];
            const float a3 = As[ty4 + 3][k];
            const float4 b = *reinterpret_cast<const float4*>(&Bs[k][tx4]);
            acc[0][0] = fmaf(a0, b.x, acc[0][0]);
            acc[0][1] = fmaf(a0, b.y, acc[0][1]);
            acc[0][2] = fmaf(a0, b.z, acc[0][2]);
            acc[0][3] = fmaf(a0, b.w, acc[0][3]);
            acc[1][0] = fmaf(a1, b.x, acc[1][0]);
            acc[1][1] = fmaf(a1, b.y, acc[1][1]);
            acc[1][2] = fmaf(a1, b.z, acc[1][2]);
            acc[1][3] = fmaf(a1, b.w, acc[1][3]);
            acc[2][0] = fmaf(a2, b.x, acc[2][0]);
            acc[2][1] = fmaf(a2, b.y, acc[2][1]);
            acc[2][2] = fmaf(a2, b.z, acc[2][2]);
            acc[2][3] = fmaf(a2, b.w, acc[2][3]);
            acc[3][0] = fmaf(a3, b.x, acc[3][0]);
            acc[3][1] = fmaf(a3, b.y, acc[3][1]);
            acc[3][2] = fmaf(a3, b.z, acc[3][2]);
            acc[3][3] = fmaf(a3, b.w, acc[3][3]);
        }
        __syncthreads();
    }

    const float4 bias4 = *reinterpret_cast<const float4*>(&Bb[n0 + tx4]);
#pragma unroll
    for (int i = 0; i < 4; i++) {
        const size_t off = (size_t)(m0 + ty4 + i) * row_stride + n0 + tx4;
        float4 r;
        r.x = acc[i][0] + bias4.x;
        r.y = acc[i][1] + bias4.y;
        r.z = acc[i][2] + bias4.z;
        r.w = acc[i][3] + bias4.w;
        if (Rb) {
            const float4 a = *reinterpret_cast<const float4*>(Rb + off);
            r.x += a.x; r.y += a.y; r.z += a.z; r.w += a.w;
        }
        if (relu) {
            r.x = fmaxf(r.x, 0.f);
            r.y = fmaxf(r.y, 0.f);
            r.z = fmaxf(r.z, 0.f);
            r.w = fmaxf(r.w, 0.f);
        }
        *reinterpret_cast<float4*>(Ob + off) = r;
    }
}

// ---------------------------------------------------------------------------
// Temporal attention: one block per (h, n, b). Causal, with relative-position
// key/value tables. Only rel indices 0..32 are reachable under causality.
// smem floats: q/k/v/R 4*3960 + rk/rv 2*1056 + A0 120 + S 14400 = 32472
// ---------------------------------------------------------------------------
#define TATTN_SMEM (32472 * 4)

__global__ void __launch_bounds__(256) tattn(
    const float* __restrict__ Q, const float* __restrict__ K,
    const float* __restrict__ V,
    const float* __restrict__ relk, const float* __restrict__ relv,
    float* __restrict__ O)
{
    extern __shared__ float sm[];
    float* sq  = sm;           // [120][33]
    float* sk  = sq + 3960;    // [120][33]
    float* sv  = sk + 3960;    // [120][33]
    float* sR  = sv + 3960;    // [120][33]  R[t][j] = q[t].relk[j]
    float* srk = sR + 3960;    // [33][32]
    float* srv = srk + 1056;   // [33][32]
    float* sA0 = srv + 1056;   // [120]
    float* sS  = sA0 + 120;    // [120][120]

    const int h = blockIdx.x, n = blockIdx.y, b = blockIdx.z;
    const int tid = threadIdx.x;
    const size_t base = ((size_t)(b * TT) * NJ + n) * DIM + h * DPH;

    // load q,k,v rows (coalesced 128B per row) and rel tables
    for (int i = tid; i < TT * DPH; i += 256) {
        const int t = i >> 5, d = i & 31;
        const size_t g = base + (size_t)t * (NJ * DIM) + d;
        sq[t * 33 + d] = Q[g];
        sk[t * 33 + d] = K[g];
        sv[t * 33 + d] = V[g];
    }
    for (int i = tid; i < 33 * 32; i += 256) {
        srk[i] = relk[i];   // rows 0..32 of the [65][32] table are contiguous
        srv[i] = relv[i];
    }
    __syncthreads();

    // R[t][j] = q[t] . relk[j]
    for (int p = tid; p < TT * 33; p += 256) {
        const int t = p / 33, j = p % 33;
        const float* qa = sq + t * 33;
        const float* ra = srk + j * 32;
        float s = 0.f;
#pragma unroll
        for (int d = 0; d < 32; d++) s = fmaf(qa[d], ra[d], s);
        sR[p] = s;
    }
    __syncthreads();

    // S[t][s] = (q[t].k[s] + R[t][clip(s-t)+32]) * scale  (4x4 tiles, skip
    // fully-masked tiles; masked entries get zeroed in the softmax pass)
    const float scale = 0.17677669529663687f;  // 1/sqrt(32)
    for (int p = tid; p < 900; p += 256) {
        const int tt = (p / 30) * 4, ss = (p % 30) * 4;
        if (ss > tt + 3) continue;  // entire tile above the diagonal
        float c[4][4];
#pragma unroll
        for (int i = 0; i < 4; i++)
#pragma unroll
            for (int j = 0; j < 4; j++) c[i][j] = 0.f;
#pragma unroll
        for (int d = 0; d < 32; d++) {
            const float a0 = sq[(tt + 0) * 33 + d];
            const float a1 = sq[(tt + 1) * 33 + d];
            const float a2 = sq[(tt + 2) * 33 + d];
            const float a3 = sq[(tt + 3) * 33 + d];
            const float b0 = sk[(ss + 0) * 33 + d];
            const float b1 = sk[(ss + 1) * 33 + d];
            const float b2 = sk[(ss + 2) * 33 + d];
            const float b3 = sk[(ss + 3) * 33 + d];
            c[0][0] = fmaf(a0, b0, c[0][0]); c[0][1] = fmaf(a0, b1, c[0][1]);
            c[0][2] = fmaf(a0, b2, c[0][2]); c[0][3] = fmaf(a0, b3, c[0][3]);
            c[1][0] = fmaf(a1, b0, c[1][0]); c[1][1] = fmaf(a1, b1, c[1][1]);
            c[1][2] = fmaf(a1, b2, c[1][2]); c[1][3] = fmaf(a1, b3, c[1][3]);
            c[2][0] = fmaf(a2, b0, c[2][0]); c[2][1] = fmaf(a2, b1, c[2][1]);
            c[2][2] = fmaf(a2, b2, c[2][2]); c[2][3] = fmaf(a2, b3, c[2][3]);
            c[3][0] = fmaf(a3, b0, c[3][0]); c[3][1] = fmaf(a3, b1, c[3][1]);
            c[3][2] = fmaf(a3, b2, c[3][2]); c[3][3] = fmaf(a3, b3, c[3][3]);
        }
#pragma unroll
        for (int i = 0; i < 4; i++) {
#pragma unroll
            for (int j = 0; j < 4; j++) {
                const int t = tt + i, s = ss + j;
                int idx = s - t + 32;
                idx = idx < 0 ? 0 : (idx > 32 ? 32 : idx);
                sS[t * 120 + s] = (c[i][j] + sR[t * 33 + idx]) * scale;
            }
        }
    }
    __syncthreads();

    // softmax per row (causal), + zero masked entries, + A0 bucket sums
    {
        const int wid = tid >> 5, lane = tid & 31;
        for (int t = wid; t < TT; t += 8) {
            float* row = sS + t * 120;
            float m = -1e30f;
            for (int s = lane; s <= t; s += 32) m = fmaxf(m, row[s]);
#pragma unroll
            for (int o = 16; o > 0; o >>= 1)
                m = fmaxf(m, __shfl_xor_sync(0xffffffffu, m, o));
            float sum = 0.f;
            for (int s = lane; s <= t; s += 32) {
                const float e = __expf(row[s] - m);
                row[s] = e;
                sum += e;
            }
#pragma unroll
            for (int o = 16; o > 0; o >>= 1)
                sum += __shfl_xor_sync(0xffffffffu, sum, o);
            const float inv = 1.f / sum;
            float a0 = 0.f;
            for (int s = lane; s <= t; s += 32) {
                const float a = row[s] * inv;
                row[s] = a;
                if (s <= t - 32) a0 += a;  // clipped bucket (idx == 0)
            }
#pragma unroll
            for (int o = 16; o > 0; o >>= 1)
                a0 += __shfl_xor_sync(0xffffffffu, a0, o);
            if (lane == 0) sA0[t] = a0;
            for (int s = t + 1 + lane; s < 120; s += 32) row[s] = 0.f;
        }
    }
    __syncthreads();

    // out[t][d] = sum_s a[t][s]*v[s][d]
    //           + A0[t]*rv[0][d] + sum_{idx in [1,32]} a[t][s]*rv[idx][d]
    for (int p = tid; p < 240; p += 256) {
        const int tt = (p / 8) * 4, dd = (p % 8) * 4;
        float c[4][4];
#pragma unroll
        for (int i = 0; i < 4; i++)
#pragma unroll
            for (int j = 0; j < 4; j++) c[i][j] = 0.f;

        const int smax = tt + 3;  // tt <= 116 so smax <= 119
        for (int s = 0; s <= smax; s++) {
            const float a0s = sS[(tt + 0) * 120 + s];
            const float a1s = sS[(tt + 1) * 120 + s];
            const float a2s = sS[(tt + 2) * 120 + s];
            const float a3s = sS[(tt + 3) * 120 + s];
            const float v0 = sv[s * 33 + dd + 0];
            const float v1 = sv[s * 33 + dd + 1];
            const float v2 = sv[s * 33 + dd + 2];
            const float v3 = sv[s * 33 + dd + 3];
            c[0][0] = fmaf(a0s, v0, c[0][0]); c[0][1] = fmaf(a0s, v1, c[0][1]);
            c[0][2] = fmaf(a0s, v2, c[0][2]); c[0][3] = fmaf(a0s, v3, c[0][3]);
            c[1][0] = fmaf(a1s, v0, c[1][0]); c[1][1] = fmaf(a1s, v1, c[1][1]);
            c[1][2] = fmaf(a1s, v2, c[1][2]); c[1][3] = fmaf(a1s, v3, c[1][3]);
            c[2][0] = fmaf(a2s, v0, c[2][0]); c[2][1] = fmaf(a2s, v1, c[2][1]);
            c[2][2] = fmaf(a2s, v2, c[2][2]); c[2][3] = fmaf(a2s, v3, c[2][3]);
            c[3][0] = fmaf(a3s, v0, c[3][0]); c[3][1] = fmaf(a3s, v1, c[3][1]);
            c[3][2] = fmaf(a3s, v2, c[3][2]); c[3][3] = fmaf(a3s, v3, c[3][3]);
        }

        // clipped bucket (all s <= t-32 mapped to rel index 0)
#pragma unroll
        for (int i = 0; i < 4; i++) {
            const float a0v = sA0[tt + i];
            c[i][0] = fmaf(a0v, srv[dd + 0], c[i][0]);
            c[i][1] = fmaf(a0v, srv[dd + 1], c[i][1]);
            c[i][2] = fmaf(a0v, srv[dd + 2], c[i][2]);
            c[i][3] = fmaf(a0v, srv[dd + 3], c[i][3]);
        }
        // rel indices 1..32 (last <=32 positions per row)
        const int slo = (tt - 31) > 0 ? (tt - 31) : 0;
        for (int s = slo; s <= smax; s++) {
#pragma unroll
            for (int i = 0; i < 4; i++) {
                const int idx = s - (tt + i) + 32;
                if (idx >= 1 && idx <= 32) {
                    const float a = sS[(tt + i) * 120 + s];
                    const float* rp = srv + idx * 32 + dd;
                    c[i][0] = fmaf(a, rp[0], c[i][0]);
                    c[i][1] = fmaf(a, rp[1], c[i][1]);
                    c[i][2] = fmaf(a, rp[2], c[i][2]);
                    c[i][3] = fmaf(a, rp[3], c[i][3]);
                }
            }
        }

#pragma unroll
        for (int i = 0; i < 4; i++) {
            const size_t g = base + (size_t)(tt + i) * (NJ * DIM) + dd;
            O[g + 0] = c[i][0];
            O[g + 1] = c[i][1];
            O[g + 2] = c[i][2];
            O[g + 3] = c[i][3];
        }
    }
}

// ---------------------------------------------------------------------------
// Spatial attention: one block per (b,t); all 8 heads over N=24 joints.
// smem floats: 3*6144 + 4608 = 23040
// ---------------------------------------------------------------------------
#define SATTN_SMEM (23040 * 4)

__global__ void __launch_bounds__(256) sattn(
    const float* __restrict__ Q, const float* __restrict__ K,
    const float* __restrict__ V, float* __restrict__ O)
{
    extern __shared__ float sm[];
    float* sq = sm;            // [24][256]
    float* sk = sq + 6144;
    float* sv = sk + 6144;
    float* sS = sv + 6144;     // [8][24][24]

    const int tid = threadIdx.x;
    const size_t base = (size_t)blockIdx.x * (NJ * DIM);

    for (int i = tid; i < NJ * DIM; i += 256) {
        sq[i] = Q[base + i];
        sk[i] = K[base + i];
        sv[i] = V[base + i];
    }
    __syncthreads();

    const float scale = 0.17677669529663687f;
    for (int p = tid; p < NH * NJ * NJ; p += 256) {
        const int hh = p / (NJ * NJ);
        const int r = p % (NJ * NJ);
        const int i = r / NJ, j = r % NJ;
        const float* qa = sq + i * DIM + hh * DPH;
        const float* ka = sk + j * DIM + hh * DPH;
        float s = 0.f;
#pragma unroll
        for (int d = 0; d < 32; d++) s = fmaf(qa[d], ka[d], s);
        sS[p] = s * scale;
    }
    __syncthreads();

    // softmax: 192 rows of 24, one thread per row
    for (int r = tid; r < NH * NJ; r += 256) {
        float* row = sS + r * NJ;
        float m = -1e30f;
#pragma unroll
        for (int j = 0; j < NJ; j++) m = fmaxf(m, row[j]);
        float sum = 0.f;
#pragma unroll
        for (int j = 0; j < NJ; j++) {
            const float e = __expf(row[j] - m);
            row[j] = e;
            sum += e;
        }
        const float inv = 1.f / sum;
#pragma unroll
        for (int j = 0; j < NJ; j++) row[j] *= inv;
    }
    __syncthreads();

    for (int p = tid; p < NJ * DIM; p += 256) {
        const int hh = p / (NJ * DPH);
        const int r = p % (NJ * DPH);
        const int i = r / DPH, d = r % DPH;
        const float* arow = sS + hh * (NJ * NJ) + i * NJ;
        const float* vcol = sv + hh * DPH + d;
        float s = 0.f;
#pragma unroll
        for (int j = 0; j < NJ; j++) s = fmaf(arow[j], vcol[j * DIM], s);
        O[base + (size_t)i * DIM + hh * DPH + d] = s;
    }
}

// ---------------------------------------------------------------------------
// launch
// ---------------------------------------------------------------------------
extern "C" void kernel_launch(void* const* d_in, const int* in_sizes, int n_in,
                              void* d_out, int out_size)
{
    (void)in_sizes; (void)n_in; (void)out_size;
    const float* x    = (const float*)d_in[0];
    // d_in[1] = mask: exactly triu(1) -> handled analytically (exp underflow)
    const float* wq_t = (const float*)d_in[2];
    const float* wk_t = (const float*)d_in[3];
    const float* wv_t = (const float*)d_in[4];
    const float* bq_t = (const float*)d_in[5];
    const float* bk_t = (const float*)d_in[6];
    const float* bv_t = (const float*)d_in[7];
    const float* wo_t = (const float*)d_in[8];
    const float* bo_t = (const float*)d_in[9];
    const float* relk = (const float*)d_in[10];
    const float* relv = (const float*)d_in[11];
    const float* wq_s = (const float*)d_in[12];
    const float* wk_s = (const float*)d_in[13];
    const float* wv_s = (const float*)d_in[14];
    const float* wo_s = (const float*)d_in[15];
    const float* bq_s = (const float*)d_in[16];
    const float* bk_s = (const float*)d_in[17];
    const float* bv_s = (const float*)d_in[18];
    const float* bo_s = (const float*)d_in[19];
    const float* ff1w = (const float*)d_in[20];
    const float* ff1b = (const float*)d_in[21];
    const float* ff2w = (const float*)d_in[22];
    const float* ff2b = (const float*)d_in[23];
    float* out = (float*)d_out;

    float *dq, *dk, *dv, *dao, *dy, *dh;
    cudaGetSymbolAddress((void**)&dq, g_q);
    cudaGetSymbolAddress((void**)&dk, g_k);
    cudaGetSymbolAddress((void**)&dv, g_v);
    cudaGetSymbolAddress((void**)&dao, g_ao);
    cudaGetSymbolAddress((void**)&dy, g_y);
    cudaGetSymbolAddress((void**)&dh, g_h);

    cudaFuncSetAttribute(tattn, cudaFuncAttributeMaxDynamicSharedMemorySize,
                         TATTN_SMEM);
    cudaFuncSetAttribute(sattn, cudaFuncAttributeMaxDynamicSharedMemorySize,
                         SATTN_SMEM);

    const dim3 gj(BT / 64, DIM / 64, NJ);    // per-joint GEMMs (M=1920 each)
    const dim3 gs(ROWS / 64, DIM / 64, 1);   // shared-weight GEMMs (M=46080)

    // ---- temporal attention path ----
    gemm64<<<gj, 256>>>(x, wq_t, bq_t, nullptr, dq, NJ * DIM, DIM, DIM * DIM, DIM, 0);
    gemm64<<<gj, 256>>>(x, wk_t, bk_t, nullptr, dk, NJ * DIM, DIM, DIM * DIM, DIM, 0);
    gemm64<<<gj, 256>>>(x, wv_t, bv_t, nullptr, dv, NJ * DIM, DIM, DIM * DIM, DIM, 0);
    tattn<<<dim3(NH, NJ, BB), 256, TATTN_SMEM>>>(dq, dk, dv, relk, relv, dao);
    // y = x + t_out
    gemm64<<<gs, 256>>>(dao, wo_t, bo_t, x, dy, DIM, 0, 0, 0, 0);

    // ---- spatial attention path (input is x, not y) ----
    gemm64<<<gs, 256>>>(x, wq_s, bq_s, nullptr, dq, DIM, 0, 0, 0, 0);
    gemm64<<<gs, 256>>>(x, wk_s, bk_s, nullptr, dk, DIM, 0, 0, 0, 0);
    gemm64<<<gs, 256>>>(x, wv_s, bv_s, nullptr, dv, DIM, 0, 0, 0, 0);
    sattn<<<BT, 256, SATTN_SMEM>>>(dq, dk, dv, dao);
    // y += s_out
    gemm64<<<gs, 256>>>(dao, wo_s, bo_s, dy, dy, DIM, 0, 0, 0, 0);

    // ---- per-joint FFN + residual ----
    gemm64<<<gj, 256>>>(dy, ff1w, ff1b, nullptr, dh, NJ * DIM, DIM, DIM * DIM, DIM, 1);
    gemm64<<<gj, 256>>>(dh, ff2w, ff2b, dy, out, NJ * DIM, DIM, DIM * DIM, DIM, 0);
}

// round 9
// speedup vs baseline: 1.1001x; 1.0965x over previous
#include <cuda_runtime.h>

// ---------------------------------------------------------------------------
// dims
// ---------------------------------------------------------------------------
#define BB   16
#define TT   120
#define NJ   24
#define DIM  256
#define NH   8
#define DPH  32
#define BT   (BB * TT)        // 1920
#define ROWS (BT * NJ)        // 46080
#define NELEM (ROWS * DIM)    // 11,796,480

// ---------------------------------------------------------------------------
// scratch buffers (device globals: allocation-free per harness rules)
// ---------------------------------------------------------------------------
__device__ float g_q[NELEM];
__device__ float g_k[NELEM];
__device__ float g_v[NELEM];
__device__ float g_ao[NELEM];
__device__ float g_y[NELEM];
__device__ float g_h[NELEM];

// ---------------------------------------------------------------------------
// Generic tiled SGEMM:  Out[m][n] = sum_k X[m][k] * W[k][n] + bias[n]
//                               (+ addsrc[m][n]) (+ ReLU)
// 64x64 block tile, 4x4 per-thread microtile, K-chunks of 16.
// ---------------------------------------------------------------------------
__global__ void __launch_bounds__(256) gemm64(
    const float* __restrict__ X, const float* __restrict__ W,
    const float* __restrict__ Bv, const float* __restrict__ Rsrc,
    float* __restrict__ Out,
    int row_stride, int zoff_x, int zoff_w, int zoff_b, int relu)
{
    __shared__ __align__(16) float As[64][17];
    __shared__ __align__(16) float Bs[16][64];

    const int z = blockIdx.z;
    const float* Xb = X + (size_t)z * zoff_x;
    const float* Wb = W + (size_t)z * zoff_w;
    const float* Bb = Bv + (size_t)z * zoff_b;
    float*       Ob = Out + (size_t)z * zoff_x;
    const float* Rb = Rsrc ? (Rsrc + (size_t)z * zoff_x) : nullptr;

    const int m0 = blockIdx.x * 64;
    const int n0 = blockIdx.y * 64;
    const int tid = threadIdx.x;
    const int tx4 = (tid & 15) * 4;
    const int ty4 = (tid >> 4) * 4;

    float acc[4][4];
#pragma unroll
    for (int i = 0; i < 4; i++)
#pragma unroll
        for (int j = 0; j < 4; j++) acc[i][j] = 0.f;

    const int lk  = tid & 15;
    const int lm  = tid >> 4;
    const int ln  = tid & 63;
    const int lkb = tid >> 6;

    for (int kc = 0; kc < DIM; kc += 16) {
#pragma unroll
        for (int i = 0; i < 4; i++)
            As[lm + i * 16][lk] =
                Xb[(size_t)(m0 + lm + i * 16) * row_stride + kc + lk];
#pragma unroll
        for (int i = 0; i < 4; i++)
            Bs[lkb + i * 4][ln] =
                Wb[(size_t)(kc + lkb + i * 4) * DIM + n0 + ln];
        __syncthreads();

#pragma unroll
        for (int k = 0; k < 16; k++) {
            const float a0 = As[ty4 + 0][k];
            const float a1 = As[ty4 + 1][k];
            const float a2 = As[ty4 + 2][k];
            const float a3 = As[ty4 + 3][k];
            const float4 b = *reinterpret_cast<const float4*>(&Bs[k][tx4]);
            acc[0][0] = fmaf(a0, b.x, acc[0][0]);
            acc[0][1] = fmaf(a0, b.y, acc[0][1]);
            acc[0][2] = fmaf(a0, b.z, acc[0][2]);
            acc[0][3] = fmaf(a0, b.w, acc[0][3]);
            acc[1][0] = fmaf(a1, b.x, acc[1][0]);
            acc[1][1] = fmaf(a1, b.y, acc[1][1]);
            acc[1][2] = fmaf(a1, b.z, acc[1][2]);
            acc[1][3] = fmaf(a1, b.w, acc[1][3]);
            acc[2][0] = fmaf(a2, b.x, acc[2][0]);
            acc[2][1] = fmaf(a2, b.y, acc[2][1]);
            acc[2][2] = fmaf(a2, b.z, acc[2][2]);
            acc[2][3] = fmaf(a2, b.w, acc[2][3]);
            acc[3][0] = fmaf(a3, b.x, acc[3][0]);
            acc[3][1] = fmaf(a3, b.y, acc[3][1]);
            acc[3][2] = fmaf(a3, b.z, acc[3][2]);
            acc[3][3] = fmaf(a3, b.w, acc[3][3]);
        }
        __syncthreads();
    }

    const float4 bias4 = *reinterpret_cast<const float4*>(&Bb[n0 + tx4]);
#pragma unroll
    for (int i = 0; i < 4; i++) {
        const size_t off = (size_t)(m0 + ty4 + i) * row_stride + n0 + tx4;
        float4 r;
        r.x = acc[i][0] + bias4.x;
        r.y = acc[i][1] + bias4.y;
        r.z = acc[i][2] + bias4.z;
        r.w = acc[i][3] + bias4.w;
        if (Rb) {
            const float4 a = *reinterpret_cast<const float4*>(Rb + off);
            r.x += a.x; r.y += a.y; r.z += a.z; r.w += a.w;
        }
        if (relu) {
            r.x = fmaxf(r.x, 0.f);
            r.y = fmaxf(r.y, 0.f);
            r.z = fmaxf(r.z, 0.f);
            r.w = fmaxf(r.w, 0.f);
        }
        *reinterpret_cast<float4*>(Ob + off) = r;
    }
}

// ---------------------------------------------------------------------------
// Temporal attention, occupancy-optimized (2 CTAs/SM):
//  - S stored triangularly packed (row t has t+1 entries, off(t)=t(t+1)/2)
//  - q/k/v padded to row stride 36 for conflict-reduced float4 LDS
//  - only lower-triangle 4x4 S tiles enumerated (465 instead of 900)
// smem floats: q/k/v 3*4320 + R 3960 + rk/rv 2*1056 + A0 120 + S 7260
//            = 26412 floats = 105648 bytes  ->  2 CTAs per SM
// ---------------------------------------------------------------------------
#define QST 36                       // padded row stride for q/k/v
#define SOFF(t) (((t) * ((t) + 1)) >> 1)
#define TATTN_SMEM (26412 * 4)

__global__ void __launch_bounds__(256) tattn(
    const float* __restrict__ Q, const float* __restrict__ K,
    const float* __restrict__ V,
    const float* __restrict__ relk, const float* __restrict__ relv,
    float* __restrict__ O)
{
    extern __shared__ __align__(16) float sm[];
    float* sq  = sm;            // [120][36]
    float* sk  = sq + 4320;     // [120][36]
    float* sv  = sk + 4320;     // [120][36]
    float* sR  = sv + 4320;     // [120][33]  R[t][j] = q[t].relk[j]
    float* srk = sR + 3960;     // [33][32]
    float* srv = srk + 1056;    // [33][32]
    float* sA0 = srv + 1056;    // [120]
    float* sS  = sA0 + 120;     // triangular, 7260

    const int h = blockIdx.x, n = blockIdx.y, b = blockIdx.z;
    const int tid = threadIdx.x;
    const size_t base = ((size_t)(b * TT) * NJ + n) * DIM + h * DPH;

    // vectorized loads: q,k,v rows (128B-aligned) and rel tables
    for (int i = tid; i < TT * 8; i += 256) {
        const int t = i >> 3, d4 = (i & 7) * 4;
        const size_t g = base + (size_t)t * (NJ * DIM) + d4;
        *reinterpret_cast<float4*>(&sq[t * QST + d4]) =
            *reinterpret_cast<const float4*>(&Q[g]);
        *reinterpret_cast<float4*>(&sk[t * QST + d4]) =
            *reinterpret_cast<const float4*>(&K[g]);
        *reinterpret_cast<float4*>(&sv[t * QST + d4]) =
            *reinterpret_cast<const float4*>(&V[g]);
    }
    for (int i = tid; i < (33 * 32) / 4; i += 256) {
        *reinterpret_cast<float4*>(&srk[i * 4]) =
            *reinterpret_cast<const float4*>(&relk[i * 4]);
        *reinterpret_cast<float4*>(&srv[i * 4]) =
            *reinterpret_cast<const float4*>(&relv[i * 4]);
    }
    __syncthreads();

    // R[t][j] = q[t] . relk[j]
    for (int p = tid; p < TT * 33; p += 256) {
        const int t = p / 33, j = p % 33;
        const float* qa = sq + t * QST;
        const float* ra = srk + j * 32;
        float s = 0.f;
#pragma unroll
        for (int d = 0; d < 32; d += 4) {
            const float4 a = *reinterpret_cast<const float4*>(qa + d);
            const float4 r = *reinterpret_cast<const float4*>(ra + d);
            s = fmaf(a.x, r.x, s); s = fmaf(a.y, r.y, s);
            s = fmaf(a.z, r.z, s); s = fmaf(a.w, r.w, s);
        }
        sR[p] = s;
    }
    __syncthreads();

    // S[t][s] = (q[t].k[s] + R[t][clip(s-t)+32]) * scale, lower tiles only
    const float scale = 0.17677669529663687f;  // 1/sqrt(32)
    for (int p = tid; p < 465; p += 256) {
        // invert triangular tile index: p = ti*(ti+1)/2 + si, si <= ti
        int ti = (int)((sqrtf(8.f * (float)p + 1.f) - 1.f) * 0.5f);
        while ((ti + 1) * (ti + 2) / 2 <= p) ti++;
        while (ti * (ti + 1) / 2 > p) ti--;
        const int si = p - ti * (ti + 1) / 2;
        const int tt = ti * 4, ss = si * 4;

        float c[4][4];
#pragma unroll
        for (int i = 0; i < 4; i++)
#pragma unroll
            for (int j = 0; j < 4; j++) c[i][j] = 0.f;

#pragma unroll
        for (int d = 0; d < 32; d += 4) {
            float4 aq[4], bk[4];
#pragma unroll
            for (int i = 0; i < 4; i++)
                aq[i] = *reinterpret_cast<const float4*>(&sq[(tt + i) * QST + d]);
#pragma unroll
            for (int j = 0; j < 4; j++)
                bk[j] = *reinterpret_cast<const float4*>(&sk[(ss + j) * QST + d]);
#pragma unroll
            for (int i = 0; i < 4; i++)
#pragma unroll
                for (int j = 0; j < 4; j++) {
                    c[i][j] = fmaf(aq[i].x, bk[j].x, c[i][j]);
                    c[i][j] = fmaf(aq[i].y, bk[j].y, c[i][j]);
                    c[i][j] = fmaf(aq[i].z, bk[j].z, c[i][j]);
                    c[i][j] = fmaf(aq[i].w, bk[j].w, c[i][j]);
                }
        }

#pragma unroll
        for (int i = 0; i < 4; i++) {
            const int t = tt + i;
            const int o = SOFF(t);
#pragma unroll
            for (int j = 0; j < 4; j++) {
                const int s = ss + j;
                if (s <= t) {
                    int idx = s - t + 32;
                    idx = idx < 0 ? 0 : idx;      // s <= t so idx <= 32 always
                    sS[o + s] = (c[i][j] + sR[t * 33 + idx]) * scale;
                }
            }
        }
    }
    __syncthreads();

    // softmax per (triangular) row + A0 bucket sums
    {
        const int wid = tid >> 5, lane = tid & 31;
        for (int t = wid; t < TT; t += 8) {
            float* row = sS + SOFF(t);
            float m = -1e30f;
            for (int s = lane; s <= t; s += 32) m = fmaxf(m, row[s]);
#pragma unroll
            for (int o = 16; o > 0; o >>= 1)
                m = fmaxf(m, __shfl_xor_sync(0xffffffffu, m, o));
            float sum = 0.f;
            for (int s = lane; s <= t; s += 32) {
                const float e = __expf(row[s] - m);
                row[s] = e;
                sum += e;
            }
#pragma unroll
            for (int o = 16; o > 0; o >>= 1)
                sum += __shfl_xor_sync(0xffffffffu, sum, o);
            const float inv = 1.f / sum;
            float a0 = 0.f;
            for (int s = lane; s <= t; s += 32) {
                const float a = row[s] * inv;
                row[s] = a;
                if (s <= t - 32) a0 += a;  // clipped bucket (rel idx == 0)
            }
#pragma unroll
            for (int o = 16; o > 0; o >>= 1)
                a0 += __shfl_xor_sync(0xffffffffu, a0, o);
            if (lane == 0) sA0[t] = a0;
        }
    }
    __syncthreads();

    // out[t][d] = sum_{s<=t} a[t][s]*v[s][d]
    //           + A0[t]*rv[0][d] + sum_{idx in [1,32]} a[t][s]*rv[idx][d]
    for (int p = tid; p < 240; p += 256) {
        const int tt = (p / 8) * 4, dd = (p % 8) * 4;
        const int o0 = SOFF(tt + 0), o1 = SOFF(tt + 1);
        const int o2 = SOFF(tt + 2), o3 = SOFF(tt + 3);

        float4 c0 = {0.f, 0.f, 0.f, 0.f}, c1 = c0, c2 = c0, c3 = c0;

        // main part: s < tt valid for all 4 rows
#pragma unroll 2
        for (int s = 0; s < tt; s++) {
            const float a0 = sS[o0 + s];
            const float a1 = sS[o1 + s];
            const float a2 = sS[o2 + s];
            const float a3 = sS[o3 + s];
            const float4 v = *reinterpret_cast<const float4*>(&sv[s * QST + dd]);
            c0.x = fmaf(a0, v.x, c0.x); c0.y = fmaf(a0, v.y, c0.y);
            c0.z = fmaf(a0, v.z, c0.z); c0.w = fmaf(a0, v.w, c0.w);
            c1.x = fmaf(a1, v.x, c1.x); c1.y = fmaf(a1, v.y, c1.y);
            c1.z = fmaf(a1, v.z, c1.z); c1.w = fmaf(a1, v.w, c1.w);
            c2.x = fmaf(a2, v.x, c2.x); c2.y = fmaf(a2, v.y, c2.y);
            c2.z = fmaf(a2, v.z, c2.z); c2.w = fmaf(a2, v.w, c2.w);
            c3.x = fmaf(a3, v.x, c3.x); c3.y = fmaf(a3, v.y, c3.y);
            c3.z = fmaf(a3, v.z, c3.z); c3.w = fmaf(a3, v.w, c3.w);
        }
        // diagonal tail: s in [tt, tt+3], only rows with s <= t
        float4* cc[4] = {&c0, &c1, &c2, &c3};
        const int oo[4] = {o0, o1, o2, o3};
#pragma unroll
        for (int j = 0; j < 4; j++) {
            const int s = tt + j;
            const float4 v = *reinterpret_cast<const float4*>(&sv[s * QST + dd]);
#pragma unroll
            for (int i = 0; i < 4; i++) {
                if (j <= i) {
                    const float a = sS[oo[i] + s];
                    cc[i]->x = fmaf(a, v.x, cc[i]->x);
                    cc[i]->y = fmaf(a, v.y, cc[i]->y);
                    cc[i]->z = fmaf(a, v.z, cc[i]->z);
                    cc[i]->w = fmaf(a, v.w, cc[i]->w);
                }
            }
        }

        // clipped bucket (all s <= t-32 map to rel index 0)
        {
            const float4 r0 = *reinterpret_cast<const float4*>(&srv[dd]);
#pragma unroll
            for (int i = 0; i < 4; i++) {
                const float a0v = sA0[tt + i];
                cc[i]->x = fmaf(a0v, r0.x, cc[i]->x);
                cc[i]->y = fmaf(a0v, r0.y, cc[i]->y);
                cc[i]->z = fmaf(a0v, r0.z, cc[i]->z);
                cc[i]->w = fmaf(a0v, r0.w, cc[i]->w);
            }
        }
        // rel indices 1..32 (last <=32 positions per row)
        const int slo = (tt - 31) > 0 ? (tt - 31) : 0;
        for (int s = slo; s <= tt + 3; s++) {
#pragma unroll
            for (int i = 0; i < 4; i++) {
                const int idx = s - (tt + i) + 32;
                if (idx >= 1 && idx <= 32) {   // idx<=32 also enforces s<=t
                    const float a = sS[oo[i] + s];
                    const float4 r = *reinterpret_cast<const float4*>(
                        &srv[idx * 32 + dd]);
                    cc[i]->x = fmaf(a, r.x, cc[i]->x);
                    cc[i]->y = fmaf(a, r.y, cc[i]->y);
                    cc[i]->z = fmaf(a, r.z, cc[i]->z);
                    cc[i]->w = fmaf(a, r.w, cc[i]->w);
                }
            }
        }

#pragma unroll
        for (int i = 0; i < 4; i++) {
            const size_t g = base + (size_t)(tt + i) * (NJ * DIM) + dd;
            *reinterpret_cast<float4*>(&O[g]) = *cc[i];
        }
    }
}

// ---------------------------------------------------------------------------
// Spatial attention: one block per (b,t); all 8 heads over N=24 joints.
// ---------------------------------------------------------------------------
#define SATTN_SMEM (23040 * 4)

__global__ void __launch_bounds__(256) sattn(
    const float* __restrict__ Q, const float* __restrict__ K,
    const float* __restrict__ V, float* __restrict__ O)
{
    extern __shared__ float sm[];
    float* sq = sm;            // [24][256]
    float* sk = sq + 6144;
    float* sv = sk + 6144;
    float* sS = sv + 6144;     // [8][24][24]

    const int tid = threadIdx.x;
    const size_t base = (size_t)blockIdx.x * (NJ * DIM);

    for (int i = tid; i < NJ * DIM; i += 256) {
        sq[i] = Q[base + i];
        sk[i] = K[base + i];
        sv[i] = V[base + i];
    }
    __syncthreads();

    const float scale = 0.17677669529663687f;
    for (int p = tid; p < NH * NJ * NJ; p += 256) {
        const int hh = p / (NJ * NJ);
        const int r = p % (NJ * NJ);
        const int i = r / NJ, j = r % NJ;
        const float* qa = sq + i * DIM + hh * DPH;
        const float* ka = sk + j * DIM + hh * DPH;
        float s = 0.f;
#pragma unroll
        for (int d = 0; d < 32; d++) s = fmaf(qa[d], ka[d], s);
        sS[p] = s * scale;
    }
    __syncthreads();

    for (int r = tid; r < NH * NJ; r += 256) {
        float* row = sS + r * NJ;
        float m = -1e30f;
#pragma unroll
        for (int j = 0; j < NJ; j++) m = fmaxf(m, row[j]);
        float sum = 0.f;
#pragma unroll
        for (int j = 0; j < NJ; j++) {
            const float e = __expf(row[j] - m);
            row[j] = e;
            sum += e;
        }
        const float inv = 1.f / sum;
#pragma unroll
        for (int j = 0; j < NJ; j++) row[j] *= inv;
    }
    __syncthreads();

    for (int p = tid; p < NJ * DIM; p += 256) {
        const int hh = p / (NJ * DPH);
        const int r = p % (NJ * DPH);
        const int i = r / DPH, d = r % DPH;
        const float* arow = sS + hh * (NJ * NJ) + i * NJ;
        const float* vcol = sv + hh * DPH + d;
        float s = 0.f;
#pragma unroll
        for (int j = 0; j < NJ; j++) s = fmaf(arow[j], vcol[j * DIM], s);
        O[base + (size_t)i * DIM + hh * DPH + d] = s;
    }
}

// ---------------------------------------------------------------------------
// launch
// ---------------------------------------------------------------------------
extern "C" void kernel_launch(void* const* d_in, const int* in_sizes, int n_in,
                              void* d_out, int out_size)
{
    (void)in_sizes; (void)n_in; (void)out_size;
    const float* x    = (const float*)d_in[0];
    // d_in[1] = mask: exactly triu(1) -> handled analytically (exp underflow)
    const float* wq_t = (const float*)d_in[2];
    const float* wk_t = (const float*)d_in[3];
    const float* wv_t = (const float*)d_in[4];
    const float* bq_t = (const float*)d_in[5];
    const float* bk_t = (const float*)d_in[6];
    const float* bv_t = (const float*)d_in[7];
    const float* wo_t = (const float*)d_in[8];
    const float* bo_t = (const float*)d_in[9];
    const float* relk = (const float*)d_in[10];
    const float* relv = (const float*)d_in[11];
    const float* wq_s = (const float*)d_in[12];
    const float* wk_s = (const float*)d_in[13];
    const float* wv_s = (const float*)d_in[14];
    const float* wo_s = (const float*)d_in[15];
    const float* bq_s = (const float*)d_in[16];
    const float* bk_s = (const float*)d_in[17];
    const float* bv_s = (const float*)d_in[18];
    const float* bo_s = (const float*)d_in[19];
    const float* ff1w = (const float*)d_in[20];
    const float* ff1b = (const float*)d_in[21];
    const float* ff2w = (const float*)d_in[22];
    const float* ff2b = (const float*)d_in[23];
    float* out = (float*)d_out;

    float *dq, *dk, *dv, *dao, *dy, *dh;
    cudaGetSymbolAddress((void**)&dq, g_q);
    cudaGetSymbolAddress((void**)&dk, g_k);
    cudaGetSymbolAddress((void**)&dv, g_v);
    cudaGetSymbolAddress((void**)&dao, g_ao);
    cudaGetSymbolAddress((void**)&dy, g_y);
    cudaGetSymbolAddress((void**)&dh, g_h);

    cudaFuncSetAttribute(tattn, cudaFuncAttributeMaxDynamicSharedMemorySize,
                         TATTN_SMEM);
    cudaFuncSetAttribute(sattn, cudaFuncAttributeMaxDynamicSharedMemorySize,
                         SATTN_SMEM);

    const dim3 gj(BT / 64, DIM / 64, NJ);    // per-joint GEMMs (M=1920 each)
    const dim3 gs(ROWS / 64, DIM / 64, 1);   // shared-weight GEMMs (M=46080)

    // ---- temporal attention path ----
    gemm64<<<gj, 256>>>(x, wq_t, bq_t, nullptr, dq, NJ * DIM, DIM, DIM * DIM, DIM, 0);
    gemm64<<<gj, 256>>>(x, wk_t, bk_t, nullptr, dk, NJ * DIM, DIM, DIM * DIM, DIM, 0);
    gemm64<<<gj, 256>>>(x, wv_t, bv_t, nullptr, dv, NJ * DIM, DIM, DIM * DIM, DIM, 0);
    tattn<<<dim3(NH, NJ, BB), 256, TATTN_SMEM>>>(dq, dk, dv, relk, relv, dao);
    // y = x + t_out
    gemm64<<<gs, 256>>>(dao, wo_t, bo_t, x, dy, DIM, 0, 0, 0, 0);

    // ---- spatial attention path (input is x, not y) ----
    gemm64<<<gs, 256>>>(x, wq_s, bq_s, nullptr, dq, DIM, 0, 0, 0, 0);
    gemm64<<<gs, 256>>>(x, wk_s, bk_s, nullptr, dk, DIM, 0, 0, 0, 0);
    gemm64<<<gs, 256>>>(x, wv_s, bv_s, nullptr, dv, DIM, 0, 0, 0, 0);
    sattn<<<BT, 256, SATTN_SMEM>>>(dq, dk, dv, dao);
    // y += s_out
    gemm64<<<gs, 256>>>(dao, wo_s, bo_s, dy, dy, DIM, 0, 0, 0, 0);

    // ---- per-joint FFN + residual ----
    gemm64<<<gj, 256>>>(dy, ff1w, ff1b, nullptr, dh, NJ * DIM, DIM, DIM * DIM, DIM, 1);
    gemm64<<<gj, 256>>>(dh, ff2w, ff2b, dy, out, NJ * DIM, DIM, DIM * DIM, DIM, 0);
}

// round 10
// speedup vs baseline: 1.2455x; 1.1321x over previous
#include <cuda_runtime.h>

// ---------------------------------------------------------------------------
// dims
// ---------------------------------------------------------------------------
#define BB   16
#define TT   120
#define NJ   24
#define NH   8
#define DIM  256
#define DPH  32
#define BT   (BB * TT)        // 1920
#define ROWS (BT * NJ)        // 46080
#define NELEM (ROWS * DIM)    // 11,796,480
#define NBNH (BB * NJ * NH)   // 3072

// ---------------------------------------------------------------------------
// scratch buffers (device globals: allocation-free per harness rules)
// ---------------------------------------------------------------------------
__device__ float g_q[NELEM];
__device__ float g_k[NELEM];
__device__ float g_v[NELEM];
__device__ float g_ao[NELEM];
__device__ float g_y[NELEM];
__device__ float g_h[NELEM];
__device__ float g_r[(size_t)NBNH * TT * 36];   // R[(b*NJ+n)*NH+h][t][36]

// ---------------------------------------------------------------------------
// Generic tiled SGEMM:  Out[m][n] = sum_k X[m][k] * W[k][n] + bias[n]
//                               (+ addsrc[m][n]) (+ ReLU)
// 64x64 block tile, 4x4 per-thread microtile, K-chunks of 16.
// ---------------------------------------------------------------------------
__global__ void __launch_bounds__(256) gemm64(
    const float* __restrict__ X, const float* __restrict__ W,
    const float* __restrict__ Bv, const float* __restrict__ Rsrc,
    float* __restrict__ Out,
    int row_stride, int zoff_x, int zoff_w, int zoff_b, int relu)
{
    __shared__ __align__(16) float As[64][17];
    __shared__ __align__(16) float Bs[16][64];

    const int z = blockIdx.z;
    const float* Xb = X + (size_t)z * zoff_x;
    const float* Wb = W + (size_t)z * zoff_w;
    const float* Bb = Bv + (size_t)z * zoff_b;
    float*       Ob = Out + (size_t)z * zoff_x;
    const float* Rb = Rsrc ? (Rsrc + (size_t)z * zoff_x) : nullptr;

    const int m0 = blockIdx.x * 64;
    const int n0 = blockIdx.y * 64;
    const int tid = threadIdx.x;
    const int tx4 = (tid & 15) * 4;
    const int ty4 = (tid >> 4) * 4;

    float acc[4][4];
#pragma unroll
    for (int i = 0; i < 4; i++)
#pragma unroll
        for (int j = 0; j < 4; j++) acc[i][j] = 0.f;

    const int lk  = tid & 15;
    const int lm  = tid >> 4;
    const int ln  = tid & 63;
    const int lkb = tid >> 6;

    for (int kc = 0; kc < DIM; kc += 16) {
#pragma unroll
        for (int i = 0; i < 4; i++)
            As[lm + i * 16][lk] =
                Xb[(size_t)(m0 + lm + i * 16) * row_stride + kc + lk];
#pragma unroll
        for (int i = 0; i < 4; i++)
            Bs[lkb + i * 4][ln] =
                Wb[(size_t)(kc + lkb + i * 4) * DIM + n0 + ln];
        __syncthreads();

#pragma unroll
        for (int k = 0; k < 16; k++) {
            const float a0 = As[ty4 + 0][k];
            const float a1 = As[ty4 + 1][k];
            const float a2 = As[ty4 + 2][k];
            const float a3 = As[ty4 + 3][k];
            const float4 b = *reinterpret_cast<const float4*>(&Bs[k][tx4]);
            acc[0][0] = fmaf(a0, b.x, acc[0][0]);
            acc[0][1] = fmaf(a0, b.y, acc[0][1]);
            acc[0][2] = fmaf(a0, b.z, acc[0][2]);
            acc[0][3] = fmaf(a0, b.w, acc[0][3]);
            acc[1][0] = fmaf(a1, b.x, acc[1][0]);
            acc[1][1] = fmaf(a1, b.y, acc[1][1]);
            acc[1][2] = fmaf(a1, b.z, acc[1][2]);
            acc[1][3] = fmaf(a1, b.w, acc[1][3]);
            acc[2][0] = fmaf(a2, b.x, acc[2][0]);
            acc[2][1] = fmaf(a2, b.y, acc[2][1]);
            acc[2][2] = fmaf(a2, b.z, acc[2][2]);
            acc[2][3] = fmaf(a2, b.w, acc[2][3]);
            acc[3][0] = fmaf(a3, b.x, acc[3][0]);
            acc[3][1] = fmaf(a3, b.y, acc[3][1]);
            acc[3][2] = fmaf(a3, b.z, acc[3][2]);
            acc[3][3] = fmaf(a3, b.w, acc[3][3]);
        }
        __syncthreads();
    }

    const float4 bias4 = *reinterpret_cast<const float4*>(&Bb[n0 + tx4]);
#pragma unroll
    for (int i = 0; i < 4; i++) {
        const size_t off = (size_t)(m0 + ty4 + i) * row_stride + n0 + tx4;
        float4 r;
        r.x = acc[i][0] + bias4.x;
        r.y = acc[i][1] + bias4.y;
        r.z = acc[i][2] + bias4.z;
        r.w = acc[i][3] + bias4.w;
        if (Rb) {
            const float4 a = *reinterpret_cast<const float4*>(Rb + off);
            r.x += a.x; r.y += a.y; r.z += a.z; r.w += a.w;
        }
        if (relu) {
            r.x = fmaxf(r.x, 0.f);
            r.y = fmaxf(r.y, 0.f);
            r.z = fmaxf(r.z, 0.f);
            r.w = fmaxf(r.w, 0.f);
        }
        *reinterpret_cast<float4*>(Ob + off) = r;
    }
}

// ---------------------------------------------------------------------------
// rproj: R[(b*NJ+n)*NH+h][t][j] = q[b,t,n,h,:] . relk[j][:], j in [0,33)
// grid (NH, NJ, BB), block 128 (thread = t). Each thread reads one full
// 128B q row (fully-used cache line) and writes a coalesced 144B R row.
// ---------------------------------------------------------------------------
__global__ void __launch_bounds__(128) rproj(
    const float* __restrict__ Q, const float* __restrict__ relk,
    float* __restrict__ R)
{
    __shared__ __align__(16) float srk[33 * 32];
    const int h = blockIdx.x, n = blockIdx.y, b = blockIdx.z;
    const int tid = threadIdx.x;

    for (int i = tid; i < (33 * 32) / 4; i += 128)
        reinterpret_cast<float4*>(srk)[i] =
            reinterpret_cast<const float4*>(relk)[i];
    __syncthreads();
    if (tid >= TT) return;

    const size_t qbase = ((size_t)(b * TT + tid) * NJ + n) * DIM + h * DPH;
    float q[32];
#pragma unroll
    for (int i = 0; i < 8; i++)
        *reinterpret_cast<float4*>(&q[i * 4]) =
            *reinterpret_cast<const float4*>(&Q[qbase + i * 4]);

    float* out = R + ((size_t)((b * NJ + n) * NH + h) * TT + tid) * 36;
#pragma unroll 3
    for (int j = 0; j < 33; j++) {
        const float* rk = srk + j * 32;
        float s0 = 0.f, s1 = 0.f, s2 = 0.f, s3 = 0.f;
#pragma unroll
        for (int d = 0; d < 32; d += 4) {
            s0 = fmaf(q[d + 0], rk[d + 0], s0);
            s1 = fmaf(q[d + 1], rk[d + 1], s1);
            s2 = fmaf(q[d + 2], rk[d + 2], s2);
            s3 = fmaf(q[d + 3], rk[d + 3], s3);
        }
        out[j] = (s0 + s1) + (s2 + s3);
    }
    out[33] = 0.f; out[34] = 0.f; out[35] = 0.f;
}

// ---------------------------------------------------------------------------
// Temporal attention v3 (conflict-free smem):
//  - q,k stored TRANSPOSED in smem [d][t] stride 124: the QK 4x4 outer
//    product loads one q-float4 (broadcast-heavy) + one k-float4 that is
//    contiguous across consecutive lanes -> conflict-free crossbar.
//  - R (q . relk) precomputed by rproj, loaded coalesced.
//  - S triangularly packed; v row-major [t][36] (AV pass conflict-free).
// smem floats: sQT 3968 + sKT 3968 + sv 4320 + sR 4320 + srv 1056
//            + sA0 120 + sS 7260 = 25012 -> 100048 B -> 2 CTAs/SM
// ---------------------------------------------------------------------------
#define TST 124                      // t-stride for transposed q/k
#define VST 36                       // row stride for v and R
#define SOFF(t) (((t) * ((t) + 1)) >> 1)
#define TATTN_SMEM (25012 * 4)

__global__ void __launch_bounds__(256) tattn(
    const float* __restrict__ Q, const float* __restrict__ K,
    const float* __restrict__ V, const float* __restrict__ Rg,
    const float* __restrict__ relv, float* __restrict__ O)
{
    extern __shared__ __align__(16) float sm[];
    float* sQT = sm;             // [32][124]
    float* sKT = sQT + 3968;     // [32][124]
    float* sv  = sKT + 3968;     // [120][36]
    float* sR  = sv + 4320;      // [120][36]
    float* srv = sR + 4320;      // [33][32]
    float* sA0 = srv + 1056;     // [120]
    float* sS  = sA0 + 120;      // triangular, 7260

    const int h = blockIdx.x, n = blockIdx.y, b = blockIdx.z;
    const int tid = threadIdx.x;
    const size_t base = ((size_t)(b * TT) * NJ + n) * DIM + h * DPH;

    // load q,k (transposed), v (row-major), R (coalesced), relv
    for (int i = tid; i < TT * 8; i += 256) {
        const int t = i >> 3, d4 = (i & 7) * 4;
        const size_t g = base + (size_t)t * (NJ * DIM) + d4;
        const float4 q4 = *reinterpret_cast<const float4*>(&Q[g]);
        const float4 k4 = *reinterpret_cast<const float4*>(&K[g]);
        const float4 v4 = *reinterpret_cast<const float4*>(&V[g]);
        *reinterpret_cast<float4*>(&sv[t * VST + d4]) = v4;
        sQT[(d4 + 0) * TST + t] = q4.x;
        sQT[(d4 + 1) * TST + t] = q4.y;
        sQT[(d4 + 2) * TST + t] = q4.z;
        sQT[(d4 + 3) * TST + t] = q4.w;
        sKT[(d4 + 0) * TST + t] = k4.x;
        sKT[(d4 + 1) * TST + t] = k4.y;
        sKT[(d4 + 2) * TST + t] = k4.z;
        sKT[(d4 + 3) * TST + t] = k4.w;
    }
    {
        const float* rg = Rg + (size_t)((b * NJ + n) * NH + h) * TT * 36;
        for (int i = tid; i < (TT * 36) / 4; i += 256)
            reinterpret_cast<float4*>(sR)[i] =
                reinterpret_cast<const float4*>(rg)[i];
    }
    for (int i = tid; i < (33 * 32) / 4; i += 256)
        reinterpret_cast<float4*>(srv)[i] =
            reinterpret_cast<const float4*>(relv)[i];
    __syncthreads();

    // S[t][s] = (q[t].k[s] + R[t][clip(s-t)+32]) * scale, lower tiles only
    const float scale = 0.17677669529663687f;  // 1/sqrt(32)
    for (int p = tid; p < 465; p += 256) {
        // invert triangular tile index: p = ti*(ti+1)/2 + si, si <= ti
        int ti = (int)((sqrtf(8.f * (float)p + 1.f) - 1.f) * 0.5f);
        while ((ti + 1) * (ti + 2) / 2 <= p) ti++;
        while (ti * (ti + 1) / 2 > p) ti--;
        const int si = p - ti * (ti + 1) / 2;
        const int tt = ti * 4, ss = si * 4;

        float c[4][4];
#pragma unroll
        for (int i = 0; i < 4; i++)
#pragma unroll
            for (int j = 0; j < 4; j++) c[i][j] = 0.f;

#pragma unroll
        for (int d = 0; d < 32; d++) {
            const float4 a = *reinterpret_cast<const float4*>(&sQT[d * TST + tt]);
            const float4 k4 = *reinterpret_cast<const float4*>(&sKT[d * TST + ss]);
            c[0][0] = fmaf(a.x, k4.x, c[0][0]); c[0][1] = fmaf(a.x, k4.y, c[0][1]);
            c[0][2] = fmaf(a.x, k4.z, c[0][2]); c[0][3] = fmaf(a.x, k4.w, c[0][3]);
            c[1][0] = fmaf(a.y, k4.x, c[1][0]); c[1][1] = fmaf(a.y, k4.y, c[1][1]);
            c[1][2] = fmaf(a.y, k4.z, c[1][2]); c[1][3] = fmaf(a.y, k4.w, c[1][3]);
            c[2][0] = fmaf(a.z, k4.x, c[2][0]); c[2][1] = fmaf(a.z, k4.y, c[2][1]);
            c[2][2] = fmaf(a.z, k4.z, c[2][2]); c[2][3] = fmaf(a.z, k4.w, c[2][3]);
            c[3][0] = fmaf(a.w, k4.x, c[3][0]); c[3][1] = fmaf(a.w, k4.y, c[3][1]);
            c[3][2] = fmaf(a.w, k4.z, c[3][2]); c[3][3] = fmaf(a.w, k4.w, c[3][3]);
        }

#pragma unroll
        for (int i = 0; i < 4; i++) {
            const int t = tt + i;
            const int o = SOFF(t);
#pragma unroll
            for (int j = 0; j < 4; j++) {
                const int s = ss + j;
                if (s <= t) {
                    int idx = s - t + 32;
                    idx = idx < 0 ? 0 : idx;   // s <= t so idx <= 32 always
                    sS[o + s] = (c[i][j] + sR[t * VST + idx]) * scale;
                }
            }
        }
    }
    __syncthreads();

    // softmax per (triangular) row + A0 bucket sums
    {
        const int wid = tid >> 5, lane = tid & 31;
        for (int t = wid; t < TT; t += 8) {
            float* row = sS + SOFF(t);
            float m = -1e30f;
            for (int s = lane; s <= t; s += 32) m = fmaxf(m, row[s]);
#pragma unroll
            for (int o = 16; o > 0; o >>= 1)
                m = fmaxf(m, __shfl_xor_sync(0xffffffffu, m, o));
            float sum = 0.f;
            for (int s = lane; s <= t; s += 32) {
                const float e = __expf(row[s] - m);
                row[s] = e;
                sum += e;
            }
#pragma unroll
            for (int o = 16; o > 0; o >>= 1)
                sum += __shfl_xor_sync(0xffffffffu, sum, o);
            const float inv = 1.f / sum;
            float a0 = 0.f;
            for (int s = lane; s <= t; s += 32) {
                const float a = row[s] * inv;
                row[s] = a;
                if (s <= t - 32) a0 += a;  // clipped bucket (rel idx == 0)
            }
#pragma unroll
            for (int o = 16; o > 0; o >>= 1)
                a0 += __shfl_xor_sync(0xffffffffu, a0, o);
            if (lane == 0) sA0[t] = a0;
        }
    }
    __syncthreads();

    // out[t][d] = sum_{s<=t} a[t][s]*v[s][d]
    //           + A0[t]*rv[0][d] + sum_{idx in [1,32]} a[t][s]*rv[idx][d]
    for (int p = tid; p < 240; p += 256) {
        const int tt = (p / 8) * 4, dd = (p % 8) * 4;
        const int o0 = SOFF(tt + 0), o1 = SOFF(tt + 1);
        const int o2 = SOFF(tt + 2), o3 = SOFF(tt + 3);

        float4 c0 = {0.f, 0.f, 0.f, 0.f}, c1 = c0, c2 = c0, c3 = c0;

        // main part: s < tt valid for all 4 rows
#pragma unroll 2
        for (int s = 0; s < tt; s++) {
            const float a0 = sS[o0 + s];
            const float a1 = sS[o1 + s];
            const float a2 = sS[o2 + s];
            const float a3 = sS[o3 + s];
            const float4 v = *reinterpret_cast<const float4*>(&sv[s * VST + dd]);
            c0.x = fmaf(a0, v.x, c0.x); c0.y = fmaf(a0, v.y, c0.y);
            c0.z = fmaf(a0, v.z, c0.z); c0.w = fmaf(a0, v.w, c0.w);
            c1.x = fmaf(a1, v.x, c1.x); c1.y = fmaf(a1, v.y, c1.y);
            c1.z = fmaf(a1, v.z, c1.z); c1.w = fmaf(a1, v.w, c1.w);
            c2.x = fmaf(a2, v.x, c2.x); c2.y = fmaf(a2, v.y, c2.y);
            c2.z = fmaf(a2, v.z, c2.z); c2.w = fmaf(a2, v.w, c2.w);
            c3.x = fmaf(a3, v.x, c3.x); c3.y = fmaf(a3, v.y, c3.y);
            c3.z = fmaf(a3, v.z, c3.z); c3.w = fmaf(a3, v.w, c3.w);
        }
        // diagonal tail: s in [tt, tt+3], only rows with s <= t
        float4* cc[4] = {&c0, &c1, &c2, &c3};
        const int oo[4] = {o0, o1, o2, o3};
#pragma unroll
        for (int j = 0; j < 4; j++) {
            const int s = tt + j;
            const float4 v = *reinterpret_cast<const float4*>(&sv[s * VST + dd]);
#pragma unroll
            for (int i = 0; i < 4; i++) {
                if (j <= i) {
                    const float a = sS[oo[i] + s];
                    cc[i]->x = fmaf(a, v.x, cc[i]->x);
                    cc[i]->y = fmaf(a, v.y, cc[i]->y);
                    cc[i]->z = fmaf(a, v.z, cc[i]->z);
                    cc[i]->w = fmaf(a, v.w, cc[i]->w);
                }
            }
        }

        // clipped bucket (all s <= t-32 map to rel index 0)
        {
            const float4 r0 = *reinterpret_cast<const float4*>(&srv[dd]);
#pragma unroll
            for (int i = 0; i < 4; i++) {
                const float a0v = sA0[tt + i];
                cc[i]->x = fmaf(a0v, r0.x, cc[i]->x);
                cc[i]->y = fmaf(a0v, r0.y, cc[i]->y);
                cc[i]->z = fmaf(a0v, r0.z, cc[i]->z);
                cc[i]->w = fmaf(a0v, r0.w, cc[i]->w);
            }
        }
        // rel indices 1..32 (last <=32 positions per row)
        const int slo = (tt - 31) > 0 ? (tt - 31) : 0;
        for (int s = slo; s <= tt + 3; s++) {
#pragma unroll
            for (int i = 0; i < 4; i++) {
                const int idx = s - (tt + i) + 32;
                if (idx >= 1 && idx <= 32) {   // idx<=32 also enforces s<=t
                    const float a = sS[oo[i] + s];
                    const float4 r = *reinterpret_cast<const float4*>(
                        &srv[idx * 32 + dd]);
                    cc[i]->x = fmaf(a, r.x, cc[i]->x);
                    cc[i]->y = fmaf(a, r.y, cc[i]->y);
                    cc[i]->z = fmaf(a, r.z, cc[i]->z);
                    cc[i]->w = fmaf(a, r.w, cc[i]->w);
                }
            }
        }

#pragma unroll
        for (int i = 0; i < 4; i++) {
            const size_t g = base + (size_t)(tt + i) * (NJ * DIM) + dd;
            *reinterpret_cast<float4*>(&O[g]) = *cc[i];
        }
    }
}

// ---------------------------------------------------------------------------
// Spatial attention: one block per (b,t); all 8 heads over N=24 joints.
// ---------------------------------------------------------------------------
#define SATTN_SMEM (23040 * 4)

__global__ void __launch_bounds__(256) sattn(
    const float* __restrict__ Q, const float* __restrict__ K,
    const float* __restrict__ V, float* __restrict__ O)
{
    extern __shared__ float sm[];
    float* sq = sm;            // [24][256]
    float* sk = sq + 6144;
    float* sv = sk + 6144;
    float* sS = sv + 6144;     // [8][24][24]

    const int tid = threadIdx.x;
    const size_t base = (size_t)blockIdx.x * (NJ * DIM);

    for (int i = tid; i < NJ * DIM; i += 256) {
        sq[i] = Q[base + i];
        sk[i] = K[base + i];
        sv[i] = V[base + i];
    }
    __syncthreads();

    const float scale = 0.17677669529663687f;
    for (int p = tid; p < NH * NJ * NJ; p += 256) {
        const int hh = p / (NJ * NJ);
        const int r = p % (NJ * NJ);
        const int i = r / NJ, j = r % NJ;
        const float* qa = sq + i * DIM + hh * DPH;
        const float* ka = sk + j * DIM + hh * DPH;
        float s = 0.f;
#pragma unroll
        for (int d = 0; d < 32; d++) s = fmaf(qa[d], ka[d], s);
        sS[p] = s * scale;
    }
    __syncthreads();

    for (int r = tid; r < NH * NJ; r += 256) {
        float* row = sS + r * NJ;
        float m = -1e30f;
#pragma unroll
        for (int j = 0; j < NJ; j++) m = fmaxf(m, row[j]);
        float sum = 0.f;
#pragma unroll
        for (int j = 0; j < NJ; j++) {
            const float e = __expf(row[j] - m);
            row[j] = e;
            sum += e;
        }
        const float inv = 1.f / sum;
#pragma unroll
        for (int j = 0; j < NJ; j++) row[j] *= inv;
    }
    __syncthreads();

    for (int p = tid; p < NJ * DIM; p += 256) {
        const int hh = p / (NJ * DPH);
        const int r = p % (NJ * DPH);
        const int i = r / DPH, d = r % DPH;
        const float* arow = sS + hh * (NJ * NJ) + i * NJ;
        const float* vcol = sv + hh * DPH + d;
        float s = 0.f;
#pragma unroll
        for (int j = 0; j < NJ; j++) s = fmaf(arow[j], vcol[j * DIM], s);
        O[base + (size_t)i * DIM + hh * DPH + d] = s;
    }
}

// ---------------------------------------------------------------------------
// launch
// ---------------------------------------------------------------------------
extern "C" void kernel_launch(void* const* d_in, const int* in_sizes, int n_in,
                              void* d_out, int out_size)
{
    (void)in_sizes; (void)n_in; (void)out_size;
    const float* x    = (const float*)d_in[0];
    // d_in[1] = mask: exactly triu(1) -> handled analytically (exp underflow)
    const float* wq_t = (const float*)d_in[2];
    const float* wk_t = (const float*)d_in[3];
    const float* wv_t = (const float*)d_in[4];
    const float* bq_t = (const float*)d_in[5];
    const float* bk_t = (const float*)d_in[6];
    const float* bv_t = (const float*)d_in[7];
    const float* wo_t = (const float*)d_in[8];
    const float* bo_t = (const float*)d_in[9];
    const float* relk = (const float*)d_in[10];
    const float* relv = (const float*)d_in[11];
    const float* wq_s = (const float*)d_in[12];
    const float* wk_s = (const float*)d_in[13];
    const float* wv_s = (const float*)d_in[14];
    const float* wo_s = (const float*)d_in[15];
    const float* bq_s = (const float*)d_in[16];
    const float* bk_s = (const float*)d_in[17];
    const float* bv_s = (const float*)d_in[18];
    const float* bo_s = (const float*)d_in[19];
    const float* ff1w = (const float*)d_in[20];
    const float* ff1b = (const float*)d_in[21];
    const float* ff2w = (const float*)d_in[22];
    const float* ff2b = (const float*)d_in[23];
    float* out = (float*)d_out;

    float *dq, *dk, *dv, *dao, *dy, *dh, *dr;
    cudaGetSymbolAddress((void**)&dq, g_q);
    cudaGetSymbolAddress((void**)&dk, g_k);
    cudaGetSymbolAddress((void**)&dv, g_v);
    cudaGetSymbolAddress((void**)&dao, g_ao);
    cudaGetSymbolAddress((void**)&dy, g_y);
    cudaGetSymbolAddress((void**)&dh, g_h);
    cudaGetSymbolAddress((void**)&dr, g_r);

    cudaFuncSetAttribute(tattn, cudaFuncAttributeMaxDynamicSharedMemorySize,
                         TATTN_SMEM);
    cudaFuncSetAttribute(sattn, cudaFuncAttributeMaxDynamicSharedMemorySize,
                         SATTN_SMEM);

    const dim3 gj(BT / 64, DIM / 64, NJ);    // per-joint GEMMs (M=1920 each)
    const dim3 gs(ROWS / 64, DIM / 64, 1);   // shared-weight GEMMs (M=46080)
    const dim3 gbnh(NH, NJ, BB);

    // ---- temporal attention path ----
    gemm64<<<gj, 256>>>(x, wq_t, bq_t, nullptr, dq, NJ * DIM, DIM, DIM * DIM, DIM, 0);
    rproj<<<gbnh, 128>>>(dq, relk, dr);
    gemm64<<<gj, 256>>>(x, wk_t, bk_t, nullptr, dk, NJ * DIM, DIM, DIM * DIM, DIM, 0);
    gemm64<<<gj, 256>>>(x, wv_t, bv_t, nullptr, dv, NJ * DIM, DIM, DIM * DIM, DIM, 0);
    tattn<<<gbnh, 256, TATTN_SMEM>>>(dq, dk, dv, dr, relv, dao);
    // y = x + t_out
    gemm64<<<gs, 256>>>(dao, wo_t, bo_t, x, dy, DIM, 0, 0, 0, 0);

    // ---- spatial attention path (input is x, not y) ----
    gemm64<<<gs, 256>>>(x, wq_s, bq_s, nullptr, dq, DIM, 0, 0, 0, 0);
    gemm64<<<gs, 256>>>(x, wk_s, bk_s, nullptr, dk, DIM, 0, 0, 0, 0);
    gemm64<<<gs, 256>>>(x, wv_s, bv_s, nullptr, dv, DIM, 0, 0, 0, 0);
    sattn<<<BT, 256, SATTN_SMEM>>>(dq, dk, dv, dao);
    // y += s_out
    gemm64<<<gs, 256>>>(dao, wo_s, bo_s, dy, dy, DIM, 0, 0, 0, 0);

    // ---- per-joint FFN + residual ----
    gemm64<<<gj, 256>>>(dy, ff1w, ff1b, nullptr, dh, NJ * DIM, DIM, DIM * DIM, DIM, 1);
    gemm64<<<gj, 256>>>(dh, ff2w, ff2b, dy, out, NJ * DIM, DIM, DIM * DIM, DIM, 0);
}

// round 11
// speedup vs baseline: 1.4012x; 1.1250x over previous
#include <cuda_runtime.h>

// ---------------------------------------------------------------------------
// dims
// ---------------------------------------------------------------------------
#define BB   16
#define TT   120
#define NJ   24
#define NH   8
#define DIM  256
#define DPH  32
#define BT   (BB * TT)        // 1920
#define ROWS (BT * NJ)        // 46080
#define NELEM (ROWS * DIM)    // 11,796,480
#define NBNH (BB * NJ * NH)   // 3072

// ---------------------------------------------------------------------------
// scratch buffers (device globals: allocation-free per harness rules)
// ---------------------------------------------------------------------------
__device__ float g_q[NELEM];
__device__ float g_k[NELEM];
__device__ float g_v[NELEM];
__device__ float g_ao[NELEM];
__device__ float g_y[NELEM];
__device__ float g_h[NELEM];
__device__ float g_r[(size_t)NBNH * TT * 36];   // R[(b*NJ+n)*NH+h][t][36]

// ---------------------------------------------------------------------------
// 128x128 SGEMM, 8x8 microtile, KC=16:
//   Out[m][n] = sum_k X[m][k] * W[k][n] + bias[n] (+ addsrc) (+ ReLU)
// A staged transposed As[k][m] (stride 132 keeps float4 alignment);
// per k-step: 4x LDS.128 + 64 FMA per thread.
// ---------------------------------------------------------------------------
#define KC  16
#define AST 132

__global__ void __launch_bounds__(256) gemm128(
    const float* __restrict__ X, const float* __restrict__ W,
    const float* __restrict__ Bv, const float* __restrict__ Rsrc,
    float* __restrict__ Out,
    int row_stride, int zoff_x, int zoff_w, int zoff_b, int relu)
{
    __shared__ __align__(16) float As[KC][AST];
    __shared__ __align__(16) float Bs[KC][128];

    const int z = blockIdx.z;
    const float* Xb = X + (size_t)z * zoff_x;
    const float* Wb = W + (size_t)z * zoff_w;
    const float* Bb = Bv + (size_t)z * zoff_b;
    float*       Ob = Out + (size_t)z * zoff_x;
    const float* Rb = Rsrc ? (Rsrc + (size_t)z * zoff_x) : nullptr;

    const int m0 = blockIdx.x * 128;
    const int n0 = blockIdx.y * 128;
    const int tid = threadIdx.x;
    const int tx = tid & 15;        // n-frag selector
    const int ty = tid >> 4;        // m-frag selector

    // A staging: thread loads 8 consecutive k of one m-row
    const int arow = tid >> 1;          // 0..127
    const int akq  = (tid & 1) * 8;     // 0 or 8
    // B staging: thread loads 8 consecutive n of one k-row
    const int bk = tid >> 4;            // 0..15
    const int bn = (tid & 15) * 8;      // 0..120

    float acc[8][8];
#pragma unroll
    for (int i = 0; i < 8; i++)
#pragma unroll
        for (int j = 0; j < 8; j++) acc[i][j] = 0.f;

    const float* aptr = Xb + (size_t)(m0 + arow) * row_stride + akq;
    const float* bptr = Wb + (size_t)bk * DIM + n0 + bn;

    for (int kc = 0; kc < DIM; kc += KC) {
        const float4 a0 = *reinterpret_cast<const float4*>(aptr + kc);
        const float4 a1 = *reinterpret_cast<const float4*>(aptr + kc + 4);
        const float4 b0 = *reinterpret_cast<const float4*>(bptr + (size_t)kc * DIM);
        const float4 b1 = *reinterpret_cast<const float4*>(bptr + (size_t)kc * DIM + 4);

        As[akq + 0][arow] = a0.x;
        As[akq + 1][arow] = a0.y;
        As[akq + 2][arow] = a0.z;
        As[akq + 3][arow] = a0.w;
        As[akq + 4][arow] = a1.x;
        As[akq + 5][arow] = a1.y;
        As[akq + 6][arow] = a1.z;
        As[akq + 7][arow] = a1.w;
        *reinterpret_cast<float4*>(&Bs[bk][bn])     = b0;
        *reinterpret_cast<float4*>(&Bs[bk][bn + 4]) = b1;
        __syncthreads();

#pragma unroll
        for (int k = 0; k < KC; k++) {
            const float4 alo = *reinterpret_cast<const float4*>(&As[k][ty * 4]);
            const float4 ahi = *reinterpret_cast<const float4*>(&As[k][64 + ty * 4]);
            const float4 blo = *reinterpret_cast<const float4*>(&Bs[k][tx * 4]);
            const float4 bhi = *reinterpret_cast<const float4*>(&Bs[k][64 + tx * 4]);
            const float av[8] = {alo.x, alo.y, alo.z, alo.w,
                                 ahi.x, ahi.y, ahi.z, ahi.w};
            const float bv[8] = {blo.x, blo.y, blo.z, blo.w,
                                 bhi.x, bhi.y, bhi.z, bhi.w};
#pragma unroll
            for (int i = 0; i < 8; i++)
#pragma unroll
                for (int j = 0; j < 8; j++)
                    acc[i][j] = fmaf(av[i], bv[j], acc[i][j]);
        }
        __syncthreads();
    }

    // epilogue: bias (+ residual) (+ relu)
    const float4 bias_lo = *reinterpret_cast<const float4*>(&Bb[n0 + tx * 4]);
    const float4 bias_hi = *reinterpret_cast<const float4*>(&Bb[n0 + 64 + tx * 4]);
    const float bb4[8] = {bias_lo.x, bias_lo.y, bias_lo.z, bias_lo.w,
                          bias_hi.x, bias_hi.y, bias_hi.z, bias_hi.w};

#pragma unroll
    for (int i = 0; i < 8; i++) {
        const int m = m0 + ((i < 4) ? (ty * 4 + i) : (64 + ty * 4 + i - 4));
        const size_t rbase = (size_t)m * row_stride;
#pragma unroll
        for (int jh = 0; jh < 2; jh++) {
            const int n = n0 + jh * 64 + tx * 4;
            float4 r;
            r.x = acc[i][jh * 4 + 0] + bb4[jh * 4 + 0];
            r.y = acc[i][jh * 4 + 1] + bb4[jh * 4 + 1];
            r.z = acc[i][jh * 4 + 2] + bb4[jh * 4 + 2];
            r.w = acc[i][jh * 4 + 3] + bb4[jh * 4 + 3];
            if (Rb) {
                const float4 a = *reinterpret_cast<const float4*>(Rb + rbase + n);
                r.x += a.x; r.y += a.y; r.z += a.z; r.w += a.w;
            }
            if (relu) {
                r.x = fmaxf(r.x, 0.f);
                r.y = fmaxf(r.y, 0.f);
                r.z = fmaxf(r.z, 0.f);
                r.w = fmaxf(r.w, 0.f);
            }
            *reinterpret_cast<float4*>(Ob + rbase + n) = r;
        }
    }
}

// ---------------------------------------------------------------------------
// rproj: R[(b*NJ+n)*NH+h][t][j] = q[b,t,n,h,:] . relk[j][:], j in [0,33)
// ---------------------------------------------------------------------------
__global__ void __launch_bounds__(128) rproj(
    const float* __restrict__ Q, const float* __restrict__ relk,
    float* __restrict__ R)
{
    __shared__ __align__(16) float srk[33 * 32];
    const int h = blockIdx.x, n = blockIdx.y, b = blockIdx.z;
    const int tid = threadIdx.x;

    for (int i = tid; i < (33 * 32) / 4; i += 128)
        reinterpret_cast<float4*>(srk)[i] =
            reinterpret_cast<const float4*>(relk)[i];
    __syncthreads();
    if (tid >= TT) return;

    const size_t qbase = ((size_t)(b * TT + tid) * NJ + n) * DIM + h * DPH;
    float q[32];
#pragma unroll
    for (int i = 0; i < 8; i++)
        *reinterpret_cast<float4*>(&q[i * 4]) =
            *reinterpret_cast<const float4*>(&Q[qbase + i * 4]);

    float* out = R + ((size_t)((b * NJ + n) * NH + h) * TT + tid) * 36;
#pragma unroll 3
    for (int j = 0; j < 33; j++) {
        const float* rk = srk + j * 32;
        float s0 = 0.f, s1 = 0.f, s2 = 0.f, s3 = 0.f;
#pragma unroll
        for (int d = 0; d < 32; d += 4) {
            s0 = fmaf(q[d + 0], rk[d + 0], s0);
            s1 = fmaf(q[d + 1], rk[d + 1], s1);
            s2 = fmaf(q[d + 2], rk[d + 2], s2);
            s3 = fmaf(q[d + 3], rk[d + 3], s3);
        }
        out[j] = (s0 + s1) + (s2 + s3);
    }
    out[33] = 0.f; out[34] = 0.f; out[35] = 0.f;
}

// ---------------------------------------------------------------------------
// Temporal attention (conflict-free smem; R precomputed; S triangular)
// ---------------------------------------------------------------------------
#define TST 124                      // t-stride for transposed q/k
#define VST 36                       // row stride for v and R
#define SOFF(t) (((t) * ((t) + 1)) >> 1)
#define TATTN_SMEM (25012 * 4)

__global__ void __launch_bounds__(256) tattn(
    const float* __restrict__ Q, const float* __restrict__ K,
    const float* __restrict__ V, const float* __restrict__ Rg,
    const float* __restrict__ relv, float* __restrict__ O)
{
    extern __shared__ __align__(16) float sm[];
    float* sQT = sm;             // [32][124]
    float* sKT = sQT + 3968;     // [32][124]
    float* sv  = sKT + 3968;     // [120][36]
    float* sR  = sv + 4320;      // [120][36]
    float* srv = sR + 4320;      // [33][32]
    float* sA0 = srv + 1056;     // [120]
    float* sS  = sA0 + 120;      // triangular, 7260

    const int h = blockIdx.x, n = blockIdx.y, b = blockIdx.z;
    const int tid = threadIdx.x;
    const size_t base = ((size_t)(b * TT) * NJ + n) * DIM + h * DPH;

    for (int i = tid; i < TT * 8; i += 256) {
        const int t = i >> 3, d4 = (i & 7) * 4;
        const size_t g = base + (size_t)t * (NJ * DIM) + d4;
        const float4 q4 = *reinterpret_cast<const float4*>(&Q[g]);
        const float4 k4 = *reinterpret_cast<const float4*>(&K[g]);
        const float4 v4 = *reinterpret_cast<const float4*>(&V[g]);
        *reinterpret_cast<float4*>(&sv[t * VST + d4]) = v4;
        sQT[(d4 + 0) * TST + t] = q4.x;
        sQT[(d4 + 1) * TST + t] = q4.y;
        sQT[(d4 + 2) * TST + t] = q4.z;
        sQT[(d4 + 3) * TST + t] = q4.w;
        sKT[(d4 + 0) * TST + t] = k4.x;
        sKT[(d4 + 1) * TST + t] = k4.y;
        sKT[(d4 + 2) * TST + t] = k4.z;
        sKT[(d4 + 3) * TST + t] = k4.w;
    }
    {
        const float* rg = Rg + (size_t)((b * NJ + n) * NH + h) * TT * 36;
        for (int i = tid; i < (TT * 36) / 4; i += 256)
            reinterpret_cast<float4*>(sR)[i] =
                reinterpret_cast<const float4*>(rg)[i];
    }
    for (int i = tid; i < (33 * 32) / 4; i += 256)
        reinterpret_cast<float4*>(srv)[i] =
            reinterpret_cast<const float4*>(relv)[i];
    __syncthreads();

    const float scale = 0.17677669529663687f;  // 1/sqrt(32)
    for (int p = tid; p < 465; p += 256) {
        int ti = (int)((sqrtf(8.f * (float)p + 1.f) - 1.f) * 0.5f);
        while ((ti + 1) * (ti + 2) / 2 <= p) ti++;
        while (ti * (ti + 1) / 2 > p) ti--;
        const int si = p - ti * (ti + 1) / 2;
        const int tt = ti * 4, ss = si * 4;

        float c[4][4];
#pragma unroll
        for (int i = 0; i < 4; i++)
#pragma unroll
            for (int j = 0; j < 4; j++) c[i][j] = 0.f;

#pragma unroll
        for (int d = 0; d < 32; d++) {
            const float4 a = *reinterpret_cast<const float4*>(&sQT[d * TST + tt]);
            const float4 k4 = *reinterpret_cast<const float4*>(&sKT[d * TST + ss]);
            c[0][0] = fmaf(a.x, k4.x, c[0][0]); c[0][1] = fmaf(a.x, k4.y, c[0][1]);
            c[0][2] = fmaf(a.x, k4.z, c[0][2]); c[0][3] = fmaf(a.x, k4.w, c[0][3]);
            c[1][0] = fmaf(a.y, k4.x, c[1][0]); c[1][1] = fmaf(a.y, k4.y, c[1][1]);
            c[1][2] = fmaf(a.y, k4.z, c[1][2]); c[1][3] = fmaf(a.y, k4.w, c[1][3]);
            c[2][0] = fmaf(a.z, k4.x, c[2][0]); c[2][1] = fmaf(a.z, k4.y, c[2][1]);
            c[2][2] = fmaf(a.z, k4.z, c[2][2]); c[2][3] = fmaf(a.z, k4.w, c[2][3]);
            c[3][0] = fmaf(a.w, k4.x, c[3][0]); c[3][1] = fmaf(a.w, k4.y, c[3][1]);
            c[3][2] = fmaf(a.w, k4.z, c[3][2]); c[3][3] = fmaf(a.w, k4.w, c[3][3]);
        }

#pragma unroll
        for (int i = 0; i < 4; i++) {
            const int t = tt + i;
            const int o = SOFF(t);
#pragma unroll
            for (int j = 0; j < 4; j++) {
                const int s = ss + j;
                if (s <= t) {
                    int idx = s - t + 32;
                    idx = idx < 0 ? 0 : idx;
                    sS[o + s] = (c[i][j] + sR[t * VST + idx]) * scale;
                }
            }
        }
    }
    __syncthreads();

    {
        const int wid = tid >> 5, lane = tid & 31;
        for (int t = wid; t < TT; t += 8) {
            float* row = sS + SOFF(t);
            float m = -1e30f;
            for (int s = lane; s <= t; s += 32) m = fmaxf(m, row[s]);
#pragma unroll
            for (int o = 16; o > 0; o >>= 1)
                m = fmaxf(m, __shfl_xor_sync(0xffffffffu, m, o));
            float sum = 0.f;
            for (int s = lane; s <= t; s += 32) {
                const float e = __expf(row[s] - m);
                row[s] = e;
                sum += e;
            }
#pragma unroll
            for (int o = 16; o > 0; o >>= 1)
                sum += __shfl_xor_sync(0xffffffffu, sum, o);
            const float inv = 1.f / sum;
            float a0 = 0.f;
            for (int s = lane; s <= t; s += 32) {
                const float a = row[s] * inv;
                row[s] = a;
                if (s <= t - 32) a0 += a;
            }
#pragma unroll
            for (int o = 16; o > 0; o >>= 1)
                a0 += __shfl_xor_sync(0xffffffffu, a0, o);
            if (lane == 0) sA0[t] = a0;
        }
    }
    __syncthreads();

    for (int p = tid; p < 240; p += 256) {
        const int tt = (p / 8) * 4, dd = (p % 8) * 4;
        const int o0 = SOFF(tt + 0), o1 = SOFF(tt + 1);
        const int o2 = SOFF(tt + 2), o3 = SOFF(tt + 3);

        float4 c0 = {0.f, 0.f, 0.f, 0.f}, c1 = c0, c2 = c0, c3 = c0;

#pragma unroll 2
        for (int s = 0; s < tt; s++) {
            const float a0 = sS[o0 + s];
            const float a1 = sS[o1 + s];
            const float a2 = sS[o2 + s];
            const float a3 = sS[o3 + s];
            const float4 v = *reinterpret_cast<const float4*>(&sv[s * VST + dd]);
            c0.x = fmaf(a0, v.x, c0.x); c0.y = fmaf(a0, v.y, c0.y);
            c0.z = fmaf(a0, v.z, c0.z); c0.w = fmaf(a0, v.w, c0.w);
            c1.x = fmaf(a1, v.x, c1.x); c1.y = fmaf(a1, v.y, c1.y);
            c1.z = fmaf(a1, v.z, c1.z); c1.w = fmaf(a1, v.w, c1.w);
            c2.x = fmaf(a2, v.x, c2.x); c2.y = fmaf(a2, v.y, c2.y);
            c2.z = fmaf(a2, v.z, c2.z); c2.w = fmaf(a2, v.w, c2.w);
            c3.x = fmaf(a3, v.x, c3.x); c3.y = fmaf(a3, v.y, c3.y);
            c3.z = fmaf(a3, v.z, c3.z); c3.w = fmaf(a3, v.w, c3.w);
        }
        float4* cc[4] = {&c0, &c1, &c2, &c3};
        const int oo[4] = {o0, o1, o2, o3};
#pragma unroll
        for (int j = 0; j < 4; j++) {
            const int s = tt + j;
            const float4 v = *reinterpret_cast<const float4*>(&sv[s * VST + dd]);
#pragma unroll
            for (int i = 0; i < 4; i++) {
                if (j <= i) {
                    const float a = sS[oo[i] + s];
                    cc[i]->x = fmaf(a, v.x, cc[i]->x);
                    cc[i]->y = fmaf(a, v.y, cc[i]->y);
                    cc[i]->z = fmaf(a, v.z, cc[i]->z);
                    cc[i]->w = fmaf(a, v.w, cc[i]->w);
                }
            }
        }

        {
            const float4 r0 = *reinterpret_cast<const float4*>(&srv[dd]);
#pragma unroll
            for (int i = 0; i < 4; i++) {
                const float a0v = sA0[tt + i];
                cc[i]->x = fmaf(a0v, r0.x, cc[i]->x);
                cc[i]->y = fmaf(a0v, r0.y, cc[i]->y);
                cc[i]->z = fmaf(a0v, r0.z, cc[i]->z);
                cc[i]->w = fmaf(a0v, r0.w, cc[i]->w);
            }
        }
        const int slo = (tt - 31) > 0 ? (tt - 31) : 0;
        for (int s = slo; s <= tt + 3; s++) {
#pragma unroll
            for (int i = 0; i < 4; i++) {
                const int idx = s - (tt + i) + 32;
                if (idx >= 1 && idx <= 32) {
                    const float a = sS[oo[i] + s];
                    const float4 r = *reinterpret_cast<const float4*>(
                        &srv[idx * 32 + dd]);
                    cc[i]->x = fmaf(a, r.x, cc[i]->x);
                    cc[i]->y = fmaf(a, r.y, cc[i]->y);
                    cc[i]->z = fmaf(a, r.z, cc[i]->z);
                    cc[i]->w = fmaf(a, r.w, cc[i]->w);
                }
            }
        }

#pragma unroll
        for (int i = 0; i < 4; i++) {
            const size_t g = base + (size_t)(tt + i) * (NJ * DIM) + dd;
            *reinterpret_cast<float4*>(&O[g]) = *cc[i];
        }
    }
}

// ---------------------------------------------------------------------------
// Spatial attention: one block per (b,t); all 8 heads over N=24 joints.
// ---------------------------------------------------------------------------
#define SATTN_SMEM (23040 * 4)

__global__ void __launch_bounds__(256) sattn(
    const float* __restrict__ Q, const float* __restrict__ K,
    const float* __restrict__ V, float* __restrict__ O)
{
    extern __shared__ float sm[];
    float* sq = sm;            // [24][256]
    float* sk = sq + 6144;
    float* sv = sk + 6144;
    float* sS = sv + 6144;     // [8][24][24]

    const int tid = threadIdx.x;
    const size_t base = (size_t)blockIdx.x * (NJ * DIM);

    for (int i = tid; i < NJ * DIM; i += 256) {
        sq[i] = Q[base + i];
        sk[i] = K[base + i];
        sv[i] = V[base + i];
    }
    __syncthreads();

    const float scale = 0.17677669529663687f;
    for (int p = tid; p < NH * NJ * NJ; p += 256) {
        const int hh = p / (NJ * NJ);
        const int r = p % (NJ * NJ);
        const int i = r / NJ, j = r % NJ;
        const float* qa = sq + i * DIM + hh * DPH;
        const float* ka = sk + j * DIM + hh * DPH;
        float s = 0.f;
#pragma unroll
        for (int d = 0; d < 32; d++) s = fmaf(qa[d], ka[d], s);
        sS[p] = s * scale;
    }
    __syncthreads();

    for (int r = tid; r < NH * NJ; r += 256) {
        float* row = sS + r * NJ;
        float m = -1e30f;
#pragma unroll
        for (int j = 0; j < NJ; j++) m = fmaxf(m, row[j]);
        float sum = 0.f;
#pragma unroll
        for (int j = 0; j < NJ; j++) {
            const float e = __expf(row[j] - m);
            row[j] = e;
            sum += e;
        }
        const float inv = 1.f / sum;
#pragma unroll
        for (int j = 0; j < NJ; j++) row[j] *= inv;
    }
    __syncthreads();

    for (int p = tid; p < NJ * DIM; p += 256) {
        const int hh = p / (NJ * DPH);
        const int r = p % (NJ * DPH);
        const int i = r / DPH, d = r % DPH;
        const float* arow = sS + hh * (NJ * NJ) + i * NJ;
        const float* vcol = sv + hh * DPH + d;
        float s = 0.f;
#pragma unroll
        for (int j = 0; j < NJ; j++) s = fmaf(arow[j], vcol[j * DIM], s);
        O[base + (size_t)i * DIM + hh * DPH + d] = s;
    }
}

// ---------------------------------------------------------------------------
// launch
// ---------------------------------------------------------------------------
extern "C" void kernel_launch(void* const* d_in, const int* in_sizes, int n_in,
                              void* d_out, int out_size)
{
    (void)in_sizes; (void)n_in; (void)out_size;
    const float* x    = (const float*)d_in[0];
    // d_in[1] = mask: exactly triu(1) -> handled analytically (exp underflow)
    const float* wq_t = (const float*)d_in[2];
    const float* wk_t = (const float*)d_in[3];
    const float* wv_t = (const float*)d_in[4];
    const float* bq_t = (const float*)d_in[5];
    const float* bk_t = (const float*)d_in[6];
    const float* bv_t = (const float*)d_in[7];
    const float* wo_t = (const float*)d_in[8];
    const float* bo_t = (const float*)d_in[9];
    const float* relk = (const float*)d_in[10];
    const float* relv = (const float*)d_in[11];
    const float* wq_s = (const float*)d_in[12];
    const float* wk_s = (const float*)d_in[13];
    const float* wv_s = (const float*)d_in[14];
    const float* wo_s = (const float*)d_in[15];
    const float* bq_s = (const float*)d_in[16];
    const float* bk_s = (const float*)d_in[17];
    const float* bv_s = (const float*)d_in[18];
    const float* bo_s = (const float*)d_in[19];
    const float* ff1w = (const float*)d_in[20];
    const float* ff1b = (const float*)d_in[21];
    const float* ff2w = (const float*)d_in[22];
    const float* ff2b = (const float*)d_in[23];
    float* out = (float*)d_out;

    float *dq, *dk, *dv, *dao, *dy, *dh, *dr;
    cudaGetSymbolAddress((void**)&dq, g_q);
    cudaGetSymbolAddress((void**)&dk, g_k);
    cudaGetSymbolAddress((void**)&dv, g_v);
    cudaGetSymbolAddress((void**)&dao, g_ao);
    cudaGetSymbolAddress((void**)&dy, g_y);
    cudaGetSymbolAddress((void**)&dh, g_h);
    cudaGetSymbolAddress((void**)&dr, g_r);

    cudaFuncSetAttribute(tattn, cudaFuncAttributeMaxDynamicSharedMemorySize,
                         TATTN_SMEM);
    cudaFuncSetAttribute(sattn, cudaFuncAttributeMaxDynamicSharedMemorySize,
                         SATTN_SMEM);

    const dim3 gj(BT / 128, DIM / 128, NJ);    // per-joint GEMMs (M=1920 each)
    const dim3 gs(ROWS / 128, DIM / 128, 1);   // shared-weight GEMMs (M=46080)
    const dim3 gbnh(NH, NJ, BB);

    // ---- temporal attention path ----
    gemm128<<<gj, 256>>>(x, wq_t, bq_t, nullptr, dq, NJ * DIM, DIM, DIM * DIM, DIM, 0);
    rproj<<<gbnh, 128>>>(dq, relk, dr);
    gemm128<<<gj, 256>>>(x, wk_t, bk_t, nullptr, dk, NJ * DIM, DIM, DIM * DIM, DIM, 0);
    gemm128<<<gj, 256>>>(x, wv_t, bv_t, nullptr, dv, NJ * DIM, DIM, DIM * DIM, DIM, 0);
    tattn<<<gbnh, 256, TATTN_SMEM>>>(dq, dk, dv, dr, relv, dao);
    // y = x + t_out
    gemm128<<<gs, 256>>>(dao, wo_t, bo_t, x, dy, DIM, 0, 0, 0, 0);

    // ---- spatial attention path (input is x, not y) ----
    gemm128<<<gs, 256>>>(x, wq_s, bq_s, nullptr, dq, DIM, 0, 0, 0, 0);
    gemm128<<<gs, 256>>>(x, wk_s, bk_s, nullptr, dk, DIM, 0, 0, 0, 0);
    gemm128<<<gs, 256>>>(x, wv_s, bv_s, nullptr, dv, DIM, 0, 0, 0, 0);
    sattn<<<BT, 256, SATTN_SMEM>>>(dq, dk, dv, dao);
    // y += s_out
    gemm128<<<gs, 256>>>(dao, wo_s, bo_s, dy, dy, DIM, 0, 0, 0, 0);

    // ---- per-joint FFN + residual ----
    gemm128<<<gj, 256>>>(dy, ff1w, ff1b, nullptr, dh, NJ * DIM, DIM, DIM * DIM, DIM, 1);
    gemm128<<<gj, 256>>>(dh, ff2w, ff2b, dy, out, NJ * DIM, DIM, DIM * DIM, DIM, 0);
}

// round 12
// speedup vs baseline: 1.5475x; 1.1045x over previous
#include <cuda_runtime.h>

// ---------------------------------------------------------------------------
// dims
// ---------------------------------------------------------------------------
#define BB   16
#define TT   120
#define NJ   24
#define NH   8
#define DIM  256
#define DPH  32
#define BT   (BB * TT)        // 1920
#define ROWS (BT * NJ)        // 46080
#define NELEM (ROWS * DIM)    // 11,796,480
#define NBNH (BB * NJ * NH)   // 3072

// ---------------------------------------------------------------------------
// scratch buffers (device globals: allocation-free per harness rules)
// ---------------------------------------------------------------------------
__device__ float g_q[NELEM];
__device__ float g_k[NELEM];
__device__ float g_v[NELEM];
__device__ float g_ao[NELEM];
__device__ float g_y[NELEM];
__device__ float g_h[NELEM];
__device__ float g_r[(size_t)NBNH * TT * 36];   // R[(b*NJ+n)*NH+h][t][36]

// ---------------------------------------------------------------------------
// 128x128 SGEMM core, 8x8 microtile, KC=16, software-pipelined global loads:
//   Out[m][n] = sum_k X[m][k] * W[k][n] + bias[n] (+ addsrc) (+ ReLU)
// A staged transposed As[k][m]; per k-step: 4x LDS.128 + 64 FMA per thread.
// Next chunk's LDGs are issued right after the first barrier and land in
// registers while the current chunk computes -> LDG latency fully hidden.
// ---------------------------------------------------------------------------
#define KC  16
#define AST 132

__device__ __forceinline__ void gemm_core(
    const float* __restrict__ Xb, const float* __restrict__ Wb,
    const float* __restrict__ Bb, const float* __restrict__ Rb,
    float* __restrict__ Ob, int row_stride, int relu,
    float (*As)[AST], float (*Bs)[128])
{
    const int m0 = blockIdx.x * 128;
    const int n0 = blockIdx.y * 128;
    const int tid = threadIdx.x;
    const int tx = tid & 15;        // n-frag selector
    const int ty = tid >> 4;        // m-frag selector

    // A staging: thread loads 8 consecutive k of one m-row
    const int arow = tid >> 1;          // 0..127
    const int akq  = (tid & 1) * 8;     // 0 or 8
    // B staging: thread loads 8 consecutive n of one k-row
    const int bk = tid >> 4;            // 0..15
    const int bn = (tid & 15) * 8;      // 0..120

    float acc[8][8];
#pragma unroll
    for (int i = 0; i < 8; i++)
#pragma unroll
        for (int j = 0; j < 8; j++) acc[i][j] = 0.f;

    const float* aptr = Xb + (size_t)(m0 + arow) * row_stride + akq;
    const float* bptr = Wb + (size_t)bk * DIM + n0 + bn;

    // prologue prefetch
    float4 pa0 = *reinterpret_cast<const float4*>(aptr);
    float4 pa1 = *reinterpret_cast<const float4*>(aptr + 4);
    float4 pb0 = *reinterpret_cast<const float4*>(bptr);
    float4 pb1 = *reinterpret_cast<const float4*>(bptr + 4);

    for (int kc = 0; kc < DIM; kc += KC) {
        As[akq + 0][arow] = pa0.x;
        As[akq + 1][arow] = pa0.y;
        As[akq + 2][arow] = pa0.z;
        As[akq + 3][arow] = pa0.w;
        As[akq + 4][arow] = pa1.x;
        As[akq + 5][arow] = pa1.y;
        As[akq + 6][arow] = pa1.z;
        As[akq + 7][arow] = pa1.w;
        *reinterpret_cast<float4*>(&Bs[bk][bn])     = pb0;
        *reinterpret_cast<float4*>(&Bs[bk][bn + 4]) = pb1;
        __syncthreads();

        // issue next chunk's loads; they complete during the compute below
        if (kc + KC < DIM) {
            pa0 = *reinterpret_cast<const float4*>(aptr + kc + KC);
            pa1 = *reinterpret_cast<const float4*>(aptr + kc + KC + 4);
            pb0 = *reinterpret_cast<const float4*>(bptr + (size_t)(kc + KC) * DIM);
            pb1 = *reinterpret_cast<const float4*>(bptr + (size_t)(kc + KC) * DIM + 4);
        }

#pragma unroll
        for (int k = 0; k < KC; k++) {
            const float4 alo = *reinterpret_cast<const float4*>(&As[k][ty * 4]);
            const float4 ahi = *reinterpret_cast<const float4*>(&As[k][64 + ty * 4]);
            const float4 blo = *reinterpret_cast<const float4*>(&Bs[k][tx * 4]);
            const float4 bhi = *reinterpret_cast<const float4*>(&Bs[k][64 + tx * 4]);
            const float av[8] = {alo.x, alo.y, alo.z, alo.w,
                                 ahi.x, ahi.y, ahi.z, ahi.w};
            const float bv[8] = {blo.x, blo.y, blo.z, blo.w,
                                 bhi.x, bhi.y, bhi.z, bhi.w};
#pragma unroll
            for (int i = 0; i < 8; i++)
#pragma unroll
                for (int j = 0; j < 8; j++)
                    acc[i][j] = fmaf(av[i], bv[j], acc[i][j]);
        }
        __syncthreads();
    }

    // epilogue: bias (+ residual) (+ relu)
    const float4 bias_lo = *reinterpret_cast<const float4*>(&Bb[n0 + tx * 4]);
    const float4 bias_hi = *reinterpret_cast<const float4*>(&Bb[n0 + 64 + tx * 4]);
    const float bb4[8] = {bias_lo.x, bias_lo.y, bias_lo.z, bias_lo.w,
                          bias_hi.x, bias_hi.y, bias_hi.z, bias_hi.w};

#pragma unroll
    for (int i = 0; i < 8; i++) {
        const int m = m0 + ((i < 4) ? (ty * 4 + i) : (64 + ty * 4 + i - 4));
        const size_t rbase = (size_t)m * row_stride;
#pragma unroll
        for (int jh = 0; jh < 2; jh++) {
            const int n = n0 + jh * 64 + tx * 4;
            float4 r;
            r.x = acc[i][jh * 4 + 0] + bb4[jh * 4 + 0];
            r.y = acc[i][jh * 4 + 1] + bb4[jh * 4 + 1];
            r.z = acc[i][jh * 4 + 2] + bb4[jh * 4 + 2];
            r.w = acc[i][jh * 4 + 3] + bb4[jh * 4 + 3];
            if (Rb) {
                const float4 a = *reinterpret_cast<const float4*>(Rb + rbase + n);
                r.x += a.x; r.y += a.y; r.z += a.z; r.w += a.w;
            }
            if (relu) {
                r.x = fmaxf(r.x, 0.f);
                r.y = fmaxf(r.y, 0.f);
                r.z = fmaxf(r.z, 0.f);
                r.w = fmaxf(r.w, 0.f);
            }
            *reinterpret_cast<float4*>(Ob + rbase + n) = r;
        }
    }
}

__global__ void __launch_bounds__(256, 2) gemm128(
    const float* __restrict__ X, const float* __restrict__ W,
    const float* __restrict__ Bv, const float* __restrict__ Rsrc,
    float* __restrict__ Out,
    int row_stride, int zoff_x, int zoff_w, int zoff_b, int relu)
{
    __shared__ __align__(16) float As[KC][AST];
    __shared__ __align__(16) float Bs[KC][128];
    const int z = blockIdx.z;
    gemm_core(X + (size_t)z * zoff_x, W + (size_t)z * zoff_w,
              Bv + (size_t)z * zoff_b,
              Rsrc ? (Rsrc + (size_t)z * zoff_x) : nullptr,
              Out + (size_t)z * zoff_x, row_stride, relu, As, Bs);
}

// Fused QKV: blockIdx.z = sel * nz + j; sel picks {q,k,v} weights/outputs.
__global__ void __launch_bounds__(256, 2) gemm128_qkv(
    const float* __restrict__ X,
    const float* __restrict__ W0, const float* __restrict__ W1,
    const float* __restrict__ W2,
    const float* __restrict__ B0, const float* __restrict__ B1,
    const float* __restrict__ B2,
    float* __restrict__ O0, float* __restrict__ O1, float* __restrict__ O2,
    int row_stride, int zoff_x, int zoff_w, int zoff_b, int nz)
{
    __shared__ __align__(16) float As[KC][AST];
    __shared__ __align__(16) float Bs[KC][128];
    const int z = blockIdx.z;
    const int sel = z / nz;
    const int j = z % nz;
    const float* W  = (sel == 0) ? W0 : ((sel == 1) ? W1 : W2);
    const float* Bv = (sel == 0) ? B0 : ((sel == 1) ? B1 : B2);
    float*       O  = (sel == 0) ? O0 : ((sel == 1) ? O1 : O2);
    gemm_core(X + (size_t)j * zoff_x, W + (size_t)j * zoff_w,
              Bv + (size_t)j * zoff_b, nullptr,
              O + (size_t)j * zoff_x, row_stride, 0, As, Bs);
}

// ---------------------------------------------------------------------------
// rproj: R[(b*NJ+n)*NH+h][t][j] = q[b,t,n,h,:] . relk[j][:], j in [0,33)
// ---------------------------------------------------------------------------
__global__ void __launch_bounds__(128) rproj(
    const float* __restrict__ Q, const float* __restrict__ relk,
    float* __restrict__ R)
{
    __shared__ __align__(16) float srk[33 * 32];
    const int h = blockIdx.x, n = blockIdx.y, b = blockIdx.z;
    const int tid = threadIdx.x;

    for (int i = tid; i < (33 * 32) / 4; i += 128)
        reinterpret_cast<float4*>(srk)[i] =
            reinterpret_cast<const float4*>(relk)[i];
    __syncthreads();
    if (tid >= TT) return;

    const size_t qbase = ((size_t)(b * TT + tid) * NJ + n) * DIM + h * DPH;
    float q[32];
#pragma unroll
    for (int i = 0; i < 8; i++)
        *reinterpret_cast<float4*>(&q[i * 4]) =
            *reinterpret_cast<const float4*>(&Q[qbase + i * 4]);

    float* out = R + ((size_t)((b * NJ + n) * NH + h) * TT + tid) * 36;
#pragma unroll 3
    for (int j = 0; j < 33; j++) {
        const float* rk = srk + j * 32;
        float s0 = 0.f, s1 = 0.f, s2 = 0.f, s3 = 0.f;
#pragma unroll
        for (int d = 0; d < 32; d += 4) {
            s0 = fmaf(q[d + 0], rk[d + 0], s0);
            s1 = fmaf(q[d + 1], rk[d + 1], s1);
            s2 = fmaf(q[d + 2], rk[d + 2], s2);
            s3 = fmaf(q[d + 3], rk[d + 3], s3);
        }
        out[j] = (s0 + s1) + (s2 + s3);
    }
    out[33] = 0.f; out[34] = 0.f; out[35] = 0.f;
}

// ---------------------------------------------------------------------------
// Temporal attention (conflict-free smem; R precomputed; S triangular)
// ---------------------------------------------------------------------------
#define TST 124                      // t-stride for transposed q/k
#define VST 36                       // row stride for v and R
#define SOFF(t) (((t) * ((t) + 1)) >> 1)
#define TATTN_SMEM (25012 * 4)

__global__ void __launch_bounds__(256) tattn(
    const float* __restrict__ Q, const float* __restrict__ K,
    const float* __restrict__ V, const float* __restrict__ Rg,
    const float* __restrict__ relv, float* __restrict__ O)
{
    extern __shared__ __align__(16) float sm[];
    float* sQT = sm;             // [32][124]
    float* sKT = sQT + 3968;     // [32][124]
    float* sv  = sKT + 3968;     // [120][36]
    float* sR  = sv + 4320;      // [120][36]
    float* srv = sR + 4320;      // [33][32]
    float* sA0 = srv + 1056;     // [120]
    float* sS  = sA0 + 120;      // triangular, 7260

    const int h = blockIdx.x, n = blockIdx.y, b = blockIdx.z;
    const int tid = threadIdx.x;
    const size_t base = ((size_t)(b * TT) * NJ + n) * DIM + h * DPH;

    for (int i = tid; i < TT * 8; i += 256) {
        const int t = i >> 3, d4 = (i & 7) * 4;
        const size_t g = base + (size_t)t * (NJ * DIM) + d4;
        const float4 q4 = *reinterpret_cast<const float4*>(&Q[g]);
        const float4 k4 = *reinterpret_cast<const float4*>(&K[g]);
        const float4 v4 = *reinterpret_cast<const float4*>(&V[g]);
        *reinterpret_cast<float4*>(&sv[t * VST + d4]) = v4;
        sQT[(d4 + 0) * TST + t] = q4.x;
        sQT[(d4 + 1) * TST + t] = q4.y;
        sQT[(d4 + 2) * TST + t] = q4.z;
        sQT[(d4 + 3) * TST + t] = q4.w;
        sKT[(d4 + 0) * TST + t] = k4.x;
        sKT[(d4 + 1) * TST + t] = k4.y;
        sKT[(d4 + 2) * TST + t] = k4.z;
        sKT[(d4 + 3) * TST + t] = k4.w;
    }
    {
        const float* rg = Rg + (size_t)((b * NJ + n) * NH + h) * TT * 36;
        for (int i = tid; i < (TT * 36) / 4; i += 256)
            reinterpret_cast<float4*>(sR)[i] =
                reinterpret_cast<const float4*>(rg)[i];
    }
    for (int i = tid; i < (33 * 32) / 4; i += 256)
        reinterpret_cast<float4*>(srv)[i] =
            reinterpret_cast<const float4*>(relv)[i];
    __syncthreads();

    const float scale = 0.17677669529663687f;  // 1/sqrt(32)
    for (int p = tid; p < 465; p += 256) {
        int ti = (int)((sqrtf(8.f * (float)p + 1.f) - 1.f) * 0.5f);
        while ((ti + 1) * (ti + 2) / 2 <= p) ti++;
        while (ti * (ti + 1) / 2 > p) ti--;
        const int si = p - ti * (ti + 1) / 2;
        const int tt = ti * 4, ss = si * 4;

        float c[4][4];
#pragma unroll
        for (int i = 0; i < 4; i++)
#pragma unroll
            for (int j = 0; j < 4; j++) c[i][j] = 0.f;

#pragma unroll
        for (int d = 0; d < 32; d++) {
            const float4 a = *reinterpret_cast<const float4*>(&sQT[d * TST + tt]);
            const float4 k4 = *reinterpret_cast<const float4*>(&sKT[d * TST + ss]);
            c[0][0] = fmaf(a.x, k4.x, c[0][0]); c[0][1] = fmaf(a.x, k4.y, c[0][1]);
            c[0][2] = fmaf(a.x, k4.z, c[0][2]); c[0][3] = fmaf(a.x, k4.w, c[0][3]);
            c[1][0] = fmaf(a.y, k4.x, c[1][0]); c[1][1] = fmaf(a.y, k4.y, c[1][1]);
            c[1][2] = fmaf(a.y, k4.z, c[1][2]); c[1][3] = fmaf(a.y, k4.w, c[1][3]);
            c[2][0] = fmaf(a.z, k4.x, c[2][0]); c[2][1] = fmaf(a.z, k4.y, c[2][1]);
            c[2][2] = fmaf(a.z, k4.z, c[2][2]); c[2][3] = fmaf(a.z, k4.w, c[2][3]);
            c[3][0] = fmaf(a.w, k4.x, c[3][0]); c[3][1] = fmaf(a.w, k4.y, c[3][1]);
            c[3][2] = fmaf(a.w, k4.z, c[3][2]); c[3][3] = fmaf(a.w, k4.w, c[3][3]);
        }

#pragma unroll
        for (int i = 0; i < 4; i++) {
            const int t = tt + i;
            const int o = SOFF(t);
#pragma unroll
            for (int j = 0; j < 4; j++) {
                const int s = ss + j;
                if (s <= t) {
                    int idx = s - t + 32;
                    idx = idx < 0 ? 0 : idx;
                    sS[o + s] = (c[i][j] + sR[t * VST + idx]) * scale;
                }
            }
        }
    }
    __syncthreads();

    {
        const int wid = tid >> 5, lane = tid & 31;
        for (int t = wid; t < TT; t += 8) {
            float* row = sS + SOFF(t);
            float m = -1e30f;
            for (int s = lane; s <= t; s += 32) m = fmaxf(m, row[s]);
#pragma unroll
            for (int o = 16; o > 0; o >>= 1)
                m = fmaxf(m, __shfl_xor_sync(0xffffffffu, m, o));
            float sum = 0.f;
            for (int s = lane; s <= t; s += 32) {
                const float e = __expf(row[s] - m);
                row[s] = e;
                sum += e;
            }
#pragma unroll
            for (int o = 16; o > 0; o >>= 1)
                sum += __shfl_xor_sync(0xffffffffu, sum, o);
            const float inv = 1.f / sum;
            float a0 = 0.f;
            for (int s = lane; s <= t; s += 32) {
                const float a = row[s] * inv;
                row[s] = a;
                if (s <= t - 32) a0 += a;
            }
#pragma unroll
            for (int o = 16; o > 0; o >>= 1)
                a0 += __shfl_xor_sync(0xffffffffu, a0, o);
            if (lane == 0) sA0[t] = a0;
        }
    }
    __syncthreads();

    for (int p = tid; p < 240; p += 256) {
        const int tt = (p / 8) * 4, dd = (p % 8) * 4;
        const int o0 = SOFF(tt + 0), o1 = SOFF(tt + 1);
        const int o2 = SOFF(tt + 2), o3 = SOFF(tt + 3);

        float4 c0 = {0.f, 0.f, 0.f, 0.f}, c1 = c0, c2 = c0, c3 = c0;

#pragma unroll 2
        for (int s = 0; s < tt; s++) {
            const float a0 = sS[o0 + s];
            const float a1 = sS[o1 + s];
            const float a2 = sS[o2 + s];
            const float a3 = sS[o3 + s];
            const float4 v = *reinterpret_cast<const float4*>(&sv[s * VST + dd]);
            c0.x = fmaf(a0, v.x, c0.x); c0.y = fmaf(a0, v.y, c0.y);
            c0.z = fmaf(a0, v.z, c0.z); c0.w = fmaf(a0, v.w, c0.w);
            c1.x = fmaf(a1, v.x, c1.x); c1.y = fmaf(a1, v.y, c1.y);
            c1.z = fmaf(a1, v.z, c1.z); c1.w = fmaf(a1, v.w, c1.w);
            c2.x = fmaf(a2, v.x, c2.x); c2.y = fmaf(a2, v.y, c2.y);
            c2.z = fmaf(a2, v.z, c2.z); c2.w = fmaf(a2, v.w, c2.w);
            c3.x = fmaf(a3, v.x, c3.x); c3.y = fmaf(a3, v.y, c3.y);
            c3.z = fmaf(a3, v.z, c3.z); c3.w = fmaf(a3, v.w, c3.w);
        }
        float4* cc[4] = {&c0, &c1, &c2, &c3};
        const int oo[4] = {o0, o1, o2, o3};
#pragma unroll
        for (int j = 0; j < 4; j++) {
            const int s = tt + j;
            const float4 v = *reinterpret_cast<const float4*>(&sv[s * VST + dd]);
#pragma unroll
            for (int i = 0; i < 4; i++) {
                if (j <= i) {
                    const float a = sS[oo[i] + s];
                    cc[i]->x = fmaf(a, v.x, cc[i]->x);
                    cc[i]->y = fmaf(a, v.y, cc[i]->y);
                    cc[i]->z = fmaf(a, v.z, cc[i]->z);
                    cc[i]->w = fmaf(a, v.w, cc[i]->w);
                }
            }
        }

        {
            const float4 r0 = *reinterpret_cast<const float4*>(&srv[dd]);
#pragma unroll
            for (int i = 0; i < 4; i++) {
                const float a0v = sA0[tt + i];
                cc[i]->x = fmaf(a0v, r0.x, cc[i]->x);
                cc[i]->y = fmaf(a0v, r0.y, cc[i]->y);
                cc[i]->z = fmaf(a0v, r0.z, cc[i]->z);
                cc[i]->w = fmaf(a0v, r0.w, cc[i]->w);
            }
        }
        const int slo = (tt - 31) > 0 ? (tt - 31) : 0;
        for (int s = slo; s <= tt + 3; s++) {
#pragma unroll
            for (int i = 0; i < 4; i++) {
                const int idx = s - (tt + i) + 32;
                if (idx >= 1 && idx <= 32) {
                    const float a = sS[oo[i] + s];
                    const float4 r = *reinterpret_cast<const float4*>(
                        &srv[idx * 32 + dd]);
                    cc[i]->x = fmaf(a, r.x, cc[i]->x);
                    cc[i]->y = fmaf(a, r.y, cc[i]->y);
                    cc[i]->z = fmaf(a, r.z, cc[i]->z);
                    cc[i]->w = fmaf(a, r.w, cc[i]->w);
                }
            }
        }

#pragma unroll
        for (int i = 0; i < 4; i++) {
            const size_t g = base + (size_t)(tt + i) * (NJ * DIM) + dd;
            *reinterpret_cast<float4*>(&O[g]) = *cc[i];
        }
    }
}

// ---------------------------------------------------------------------------
// Spatial attention: one block per (b,t); all 8 heads over N=24 joints.
// ---------------------------------------------------------------------------
#define SATTN_SMEM (23040 * 4)

__global__ void __launch_bounds__(256) sattn(
    const float* __restrict__ Q, const float* __restrict__ K,
    const float* __restrict__ V, float* __restrict__ O)
{
    extern __shared__ float sm[];
    float* sq = sm;            // [24][256]
    float* sk = sq + 6144;
    float* sv = sk + 6144;
    float* sS = sv + 6144;     // [8][24][24]

    const int tid = threadIdx.x;
    const size_t base = (size_t)blockIdx.x * (NJ * DIM);

    for (int i = tid; i < NJ * DIM; i += 256) {
        sq[i] = Q[base + i];
        sk[i] = K[base + i];
        sv[i] = V[base + i];
    }
    __syncthreads();

    const float scale = 0.17677669529663687f;
    for (int p = tid; p < NH * NJ * NJ; p += 256) {
        const int hh = p / (NJ * NJ);
        const int r = p % (NJ * NJ);
        const int i = r / NJ, j = r % NJ;
        const float* qa = sq + i * DIM + hh * DPH;
        const float* ka = sk + j * DIM + hh * DPH;
        float s = 0.f;
#pragma unroll
        for (int d = 0; d < 32; d++) s = fmaf(qa[d], ka[d], s);
        sS[p] = s * scale;
    }
    __syncthreads();

    for (int r = tid; r < NH * NJ; r += 256) {
        float* row = sS + r * NJ;
        float m = -1e30f;
#pragma unroll
        for (int j = 0; j < NJ; j++) m = fmaxf(m, row[j]);
        float sum = 0.f;
#pragma unroll
        for (int j = 0; j < NJ; j++) {
            const float e = __expf(row[j] - m);
            row[j] = e;
            sum += e;
        }
        const float inv = 1.f / sum;
#pragma unroll
        for (int j = 0; j < NJ; j++) row[j] *= inv;
    }
    __syncthreads();

    for (int p = tid; p < NJ * DIM; p += 256) {
        const int hh = p / (NJ * DPH);
        const int r = p % (NJ * DPH);
        const int i = r / DPH, d = r % DPH;
        const float* arow = sS + hh * (NJ * NJ) + i * NJ;
        const float* vcol = sv + hh * DPH + d;
        float s = 0.f;
#pragma unroll
        for (int j = 0; j < NJ; j++) s = fmaf(arow[j], vcol[j * DIM], s);
        O[base + (size_t)i * DIM + hh * DPH + d] = s;
    }
}

// ---------------------------------------------------------------------------
// launch
// ---------------------------------------------------------------------------
extern "C" void kernel_launch(void* const* d_in, const int* in_sizes, int n_in,
                              void* d_out, int out_size)
{
    (void)in_sizes; (void)n_in; (void)out_size;
    const float* x    = (const float*)d_in[0];
    // d_in[1] = mask: exactly triu(1) -> handled analytically (exp underflow)
    const float* wq_t = (const float*)d_in[2];
    const float* wk_t = (const float*)d_in[3];
    const float* wv_t = (const float*)d_in[4];
    const float* bq_t = (const float*)d_in[5];
    const float* bk_t = (const float*)d_in[6];
    const float* bv_t = (const float*)d_in[7];
    const float* wo_t = (const float*)d_in[8];
    const float* bo_t = (const float*)d_in[9];
    const float* relk = (const float*)d_in[10];
    const float* relv = (const float*)d_in[11];
    const float* wq_s = (const float*)d_in[12];
    const float* wk_s = (const float*)d_in[13];
    const float* wv_s = (const float*)d_in[14];
    const float* wo_s = (const float*)d_in[15];
    const float* bq_s = (const float*)d_in[16];
    const float* bk_s = (const float*)d_in[17];
    const float* bv_s = (const float*)d_in[18];
    const float* bo_s = (const float*)d_in[19];
    const float* ff1w = (const float*)d_in[20];
    const float* ff1b = (const float*)d_in[21];
    const float* ff2w = (const float*)d_in[22];
    const float* ff2b = (const float*)d_in[23];
    float* out = (float*)d_out;

    float *dq, *dk, *dv, *dao, *dy, *dh, *dr;
    cudaGetSymbolAddress((void**)&dq, g_q);
    cudaGetSymbolAddress((void**)&dk, g_k);
    cudaGetSymbolAddress((void**)&dv, g_v);
    cudaGetSymbolAddress((void**)&dao, g_ao);
    cudaGetSymbolAddress((void**)&dy, g_y);
    cudaGetSymbolAddress((void**)&dh, g_h);
    cudaGetSymbolAddress((void**)&dr, g_r);

    cudaFuncSetAttribute(tattn, cudaFuncAttributeMaxDynamicSharedMemorySize,
                         TATTN_SMEM);
    cudaFuncSetAttribute(sattn, cudaFuncAttributeMaxDynamicSharedMemorySize,
                         SATTN_SMEM);

    const dim3 gj(BT / 128, DIM / 128, NJ);        // per-joint single GEMM
    const dim3 gj3(BT / 128, DIM / 128, 3 * NJ);   // fused per-joint QKV
    const dim3 gs(ROWS / 128, DIM / 128, 1);       // shared-weight single GEMM
    const dim3 gs3(ROWS / 128, DIM / 128, 3);      // fused shared QKV
    const dim3 gbnh(NH, NJ, BB);

    // ---- temporal attention path (fused per-joint QKV) ----
    gemm128_qkv<<<gj3, 256>>>(x, wq_t, wk_t, wv_t, bq_t, bk_t, bv_t,
                              dq, dk, dv, NJ * DIM, DIM, DIM * DIM, DIM, NJ);
    rproj<<<gbnh, 128>>>(dq, relk, dr);
    tattn<<<gbnh, 256, TATTN_SMEM>>>(dq, dk, dv, dr, relv, dao);
    // y = x + t_out
    gemm128<<<gs, 256>>>(dao, wo_t, bo_t, x, dy, DIM, 0, 0, 0, 0);

    // ---- spatial attention path (fused shared QKV; input is x, not y) ----
    gemm128_qkv<<<gs3, 256>>>(x, wq_s, wk_s, wv_s, bq_s, bk_s, bv_s,
                              dq, dk, dv, DIM, 0, 0, 0, 1);
    sattn<<<BT, 256, SATTN_SMEM>>>(dq, dk, dv, dao);
    // y += s_out
    gemm128<<<gs, 256>>>(dao, wo_s, bo_s, dy, dy, DIM, 0, 0, 0, 0);

    // ---- per-joint FFN + residual ----
    gemm128<<<gj, 256>>>(dy, ff1w, ff1b, nullptr, dh, NJ * DIM, DIM, DIM * DIM, DIM, 1);
    gemm128<<<gj, 256>>>(dh, ff2w, ff2b, dy, out, NJ * DIM, DIM, DIM * DIM, DIM, 0);
}

// round 13
// speedup vs baseline: 2.1405x; 1.3832x over previous
#include <cuda_runtime.h>

// ---------------------------------------------------------------------------
// dims
// ---------------------------------------------------------------------------
#define BB   16
#define TT   120
#define NJ   24
#define NH   8
#define DIM  256
#define DPH  32
#define BT   (BB * TT)        // 1920
#define ROWS (BT * NJ)        // 46080
#define NELEM (ROWS * DIM)    // 11,796,480
#define NBNH (BB * NJ * NH)   // 3072

// ---------------------------------------------------------------------------
// scratch buffers (device globals: allocation-free per harness rules)
// ---------------------------------------------------------------------------
__device__ float g_q[NELEM];
__device__ float g_k[NELEM];
__device__ float g_v[NELEM];
__device__ float g_ao[NELEM];
__device__ float g_y[NELEM];
__device__ float g_h[NELEM];
__device__ float g_r[(size_t)NBNH * TT * 36];   // R[(b*NJ+n)*NH+h][t][36]

// ---------------------------------------------------------------------------
// tf32 tensor-core GEMM: Out[m][n] = sum_k X[m][k]*W[k][n] + bias (+res)(+relu)
// 128x128 block tile, 8 warps (2 M x 4 N), warp tile 64x32 via
// mma.sync.m16n8k8 tf32. KC=16 smem chunks with register prefetch.
// Xs stride 20 / Ws stride 136 make both fragment-load patterns bank-
// conflict-free (verified: A banks = perm(8*quad)+tq, B banks = 8*tq+quad).
// ---------------------------------------------------------------------------
#define KC  16
#define XST 20
#define WST 136

__device__ __forceinline__ unsigned int f2tf(float f) {
    unsigned int r;
    asm("cvt.rna.tf32.f32 %0, %1;" : "=r"(r) : "f"(f));
    return r;
}

__device__ __forceinline__ void mma8(
    float& d0, float& d1, float& d2, float& d3,
    unsigned int a0, unsigned int a1, unsigned int a2, unsigned int a3,
    unsigned int b0, unsigned int b1)
{
    asm volatile(
        "mma.sync.aligned.m16n8k8.row.col.f32.tf32.tf32.f32 "
        "{%0,%1,%2,%3}, {%4,%5,%6,%7}, {%8,%9}, {%0,%1,%2,%3};"
        : "+f"(d0), "+f"(d1), "+f"(d2), "+f"(d3)
        : "r"(a0), "r"(a1), "r"(a2), "r"(a3), "r"(b0), "r"(b1));
}

__device__ __forceinline__ void gemm_core(
    const float* __restrict__ Xb, const float* __restrict__ Wb,
    const float* __restrict__ Bb, const float* __restrict__ Rb,
    float* __restrict__ Ob, int row_stride, int relu,
    unsigned int (*Xs)[XST], unsigned int (*Ws)[WST])
{
    const int m0 = blockIdx.x * 128;
    const int n0 = blockIdx.y * 128;
    const int tid = threadIdx.x;
    const int warp = tid >> 5, lane = tid & 31;
    const int quad = lane >> 2, tq = lane & 3;
    const int mw = (warp & 1) * 64;      // warp M offset
    const int nw = (warp >> 1) * 32;     // warp N offset

    // staging assignments
    const int sxm = tid >> 1, sxk = (tid & 1) * 8;   // X: row sxm, k sxk..sxk+7
    const int swk = tid >> 4, swn = (tid & 15) * 8;  // W: row swk, n swn..swn+7

    float acc[4][4][4];
#pragma unroll
    for (int mt = 0; mt < 4; mt++)
#pragma unroll
        for (int nt = 0; nt < 4; nt++)
#pragma unroll
            for (int c = 0; c < 4; c++) acc[mt][nt][c] = 0.f;

    const float* xp = Xb + (size_t)(m0 + sxm) * row_stride + sxk;
    const float* wp = Wb + (size_t)swk * DIM + n0 + swn;

    // prologue prefetch
    float4 px0 = *reinterpret_cast<const float4*>(xp);
    float4 px1 = *reinterpret_cast<const float4*>(xp + 4);
    float4 pw0 = *reinterpret_cast<const float4*>(wp);
    float4 pw1 = *reinterpret_cast<const float4*>(wp + 4);

    for (int kc = 0; kc < DIM; kc += KC) {
        // convert + stage current chunk
        uint4 ua, ub;
        ua.x = f2tf(px0.x); ua.y = f2tf(px0.y);
        ua.z = f2tf(px0.z); ua.w = f2tf(px0.w);
        ub.x = f2tf(px1.x); ub.y = f2tf(px1.y);
        ub.z = f2tf(px1.z); ub.w = f2tf(px1.w);
        *reinterpret_cast<uint4*>(&Xs[sxm][sxk])     = ua;
        *reinterpret_cast<uint4*>(&Xs[sxm][sxk + 4]) = ub;
        ua.x = f2tf(pw0.x); ua.y = f2tf(pw0.y);
        ua.z = f2tf(pw0.z); ua.w = f2tf(pw0.w);
        ub.x = f2tf(pw1.x); ub.y = f2tf(pw1.y);
        ub.z = f2tf(pw1.z); ub.w = f2tf(pw1.w);
        *reinterpret_cast<uint4*>(&Ws[swk][swn])     = ua;
        *reinterpret_cast<uint4*>(&Ws[swk][swn + 4]) = ub;
        __syncthreads();

        // issue next chunk's global loads (hidden under MMA work)
        if (kc + KC < DIM) {
            px0 = *reinterpret_cast<const float4*>(xp + kc + KC);
            px1 = *reinterpret_cast<const float4*>(xp + kc + KC + 4);
            pw0 = *reinterpret_cast<const float4*>(wp + (size_t)(kc + KC) * DIM);
            pw1 = *reinterpret_cast<const float4*>(wp + (size_t)(kc + KC) * DIM + 4);
        }

#pragma unroll
        for (int ks = 0; ks < KC; ks += 8) {
            unsigned int af[4][4], bf[4][2];
#pragma unroll
            for (int mt = 0; mt < 4; mt++) {
                const int r = mw + mt * 16 + quad;
                af[mt][0] = Xs[r][ks + tq];
                af[mt][1] = Xs[r + 8][ks + tq];
                af[mt][2] = Xs[r][ks + tq + 4];
                af[mt][3] = Xs[r + 8][ks + tq + 4];
            }
#pragma unroll
            for (int nt = 0; nt < 4; nt++) {
                const int cn = nw + nt * 8 + quad;
                bf[nt][0] = Ws[ks + tq][cn];
                bf[nt][1] = Ws[ks + tq + 4][cn];
            }
#pragma unroll
            for (int mt = 0; mt < 4; mt++)
#pragma unroll
                for (int nt = 0; nt < 4; nt++)
                    mma8(acc[mt][nt][0], acc[mt][nt][1],
                         acc[mt][nt][2], acc[mt][nt][3],
                         af[mt][0], af[mt][1], af[mt][2], af[mt][3],
                         bf[nt][0], bf[nt][1]);
        }
        __syncthreads();
    }

    // epilogue: c0=(g,2tq) c1=(g,2tq+1) c2=(g+8,2tq) c3=(g+8,2tq+1)
#pragma unroll
    for (int mt = 0; mt < 4; mt++) {
        const int r0 = m0 + mw + mt * 16 + quad;
        const int r1 = r0 + 8;
#pragma unroll
        for (int nt = 0; nt < 4; nt++) {
            const int n = n0 + nw + nt * 8 + tq * 2;
            const float2 bb = *reinterpret_cast<const float2*>(&Bb[n]);
            float2 v0, v1;
            v0.x = acc[mt][nt][0] + bb.x;
            v0.y = acc[mt][nt][1] + bb.y;
            v1.x = acc[mt][nt][2] + bb.x;
            v1.y = acc[mt][nt][3] + bb.y;
            const size_t o0 = (size_t)r0 * row_stride + n;
            const size_t o1 = (size_t)r1 * row_stride + n;
            if (Rb) {
                const float2 a0 = *reinterpret_cast<const float2*>(Rb + o0);
                const float2 a1 = *reinterpret_cast<const float2*>(Rb + o1);
                v0.x += a0.x; v0.y += a0.y;
                v1.x += a1.x; v1.y += a1.y;
            }
            if (relu) {
                v0.x = fmaxf(v0.x, 0.f); v0.y = fmaxf(v0.y, 0.f);
                v1.x = fmaxf(v1.x, 0.f); v1.y = fmaxf(v1.y, 0.f);
            }
            *reinterpret_cast<float2*>(Ob + o0) = v0;
            *reinterpret_cast<float2*>(Ob + o1) = v1;
        }
    }
}

__global__ void __launch_bounds__(256, 2) gemm128(
    const float* __restrict__ X, const float* __restrict__ W,
    const float* __restrict__ Bv, const float* __restrict__ Rsrc,
    float* __restrict__ Out,
    int row_stride, int zoff_x, int zoff_w, int zoff_b, int relu)
{
    __shared__ __align__(16) unsigned int Xs[128][XST];
    __shared__ __align__(16) unsigned int Ws[KC][WST];
    const int z = blockIdx.z;
    gemm_core(X + (size_t)z * zoff_x, W + (size_t)z * zoff_w,
              Bv + (size_t)z * zoff_b,
              Rsrc ? (Rsrc + (size_t)z * zoff_x) : nullptr,
              Out + (size_t)z * zoff_x, row_stride, relu, Xs, Ws);
}

// Fused QKV: blockIdx.z = sel * nz + j; sel picks {q,k,v} weights/outputs.
__global__ void __launch_bounds__(256, 2) gemm128_qkv(
    const float* __restrict__ X,
    const float* __restrict__ W0, const float* __restrict__ W1,
    const float* __restrict__ W2,
    const float* __restrict__ B0, const float* __restrict__ B1,
    const float* __restrict__ B2,
    float* __restrict__ O0, float* __restrict__ O1, float* __restrict__ O2,
    int row_stride, int zoff_x, int zoff_w, int zoff_b, int nz)
{
    __shared__ __align__(16) unsigned int Xs[128][XST];
    __shared__ __align__(16) unsigned int Ws[KC][WST];
    const int z = blockIdx.z;
    const int sel = z / nz;
    const int j = z % nz;
    const float* W  = (sel == 0) ? W0 : ((sel == 1) ? W1 : W2);
    const float* Bv = (sel == 0) ? B0 : ((sel == 1) ? B1 : B2);
    float*       O  = (sel == 0) ? O0 : ((sel == 1) ? O1 : O2);
    gemm_core(X + (size_t)j * zoff_x, W + (size_t)j * zoff_w,
              Bv + (size_t)j * zoff_b, nullptr,
              O + (size_t)j * zoff_x, row_stride, 0, Xs, Ws);
}

// ---------------------------------------------------------------------------
// rproj: R[(b*NJ+n)*NH+h][t][j] = q[b,t,n,h,:] . relk[j][:], j in [0,33)
// ---------------------------------------------------------------------------
__global__ void __launch_bounds__(128) rproj(
    const float* __restrict__ Q, const float* __restrict__ relk,
    float* __restrict__ R)
{
    __shared__ __align__(16) float srk[33 * 32];
    const int h = blockIdx.x, n = blockIdx.y, b = blockIdx.z;
    const int tid = threadIdx.x;

    for (int i = tid; i < (33 * 32) / 4; i += 128)
        reinterpret_cast<float4*>(srk)[i] =
            reinterpret_cast<const float4*>(relk)[i];
    __syncthreads();
    if (tid >= TT) return;

    const size_t qbase = ((size_t)(b * TT + tid) * NJ + n) * DIM + h * DPH;
    float q[32];
#pragma unroll
    for (int i = 0; i < 8; i++)
        *reinterpret_cast<float4*>(&q[i * 4]) =
            *reinterpret_cast<const float4*>(&Q[qbase + i * 4]);

    float* out = R + ((size_t)((b * NJ + n) * NH + h) * TT + tid) * 36;
#pragma unroll 3
    for (int j = 0; j < 33; j++) {
        const float* rk = srk + j * 32;
        float s0 = 0.f, s1 = 0.f, s2 = 0.f, s3 = 0.f;
#pragma unroll
        for (int d = 0; d < 32; d += 4) {
            s0 = fmaf(q[d + 0], rk[d + 0], s0);
            s1 = fmaf(q[d + 1], rk[d + 1], s1);
            s2 = fmaf(q[d + 2], rk[d + 2], s2);
            s3 = fmaf(q[d + 3], rk[d + 3], s3);
        }
        out[j] = (s0 + s1) + (s2 + s3);
    }
    out[33] = 0.f; out[34] = 0.f; out[35] = 0.f;
}

// ---------------------------------------------------------------------------
// Temporal attention (conflict-free smem; R precomputed; S triangular)
// ---------------------------------------------------------------------------
#define TST 124                      // t-stride for transposed q/k
#define VST 36                       // row stride for v and R
#define SOFF(t) (((t) * ((t) + 1)) >> 1)
#define TATTN_SMEM (25012 * 4)

__global__ void __launch_bounds__(256) tattn(
    const float* __restrict__ Q, const float* __restrict__ K,
    const float* __restrict__ V, const float* __restrict__ Rg,
    const float* __restrict__ relv, float* __restrict__ O)
{
    extern __shared__ __align__(16) float sm[];
    float* sQT = sm;             // [32][124]
    float* sKT = sQT + 3968;     // [32][124]
    float* sv  = sKT + 3968;     // [120][36]
    float* sR  = sv + 4320;      // [120][36]
    float* srv = sR + 4320;      // [33][32]
    float* sA0 = srv + 1056;     // [120]
    float* sS  = sA0 + 120;      // triangular, 7260

    const int h = blockIdx.x, n = blockIdx.y, b = blockIdx.z;
    const int tid = threadIdx.x;
    const size_t base = ((size_t)(b * TT) * NJ + n) * DIM + h * DPH;

    for (int i = tid; i < TT * 8; i += 256) {
        const int t = i >> 3, d4 = (i & 7) * 4;
        const size_t g = base + (size_t)t * (NJ * DIM) + d4;
        const float4 q4 = *reinterpret_cast<const float4*>(&Q[g]);
        const float4 k4 = *reinterpret_cast<const float4*>(&K[g]);
        const float4 v4 = *reinterpret_cast<const float4*>(&V[g]);
        *reinterpret_cast<float4*>(&sv[t * VST + d4]) = v4;
        sQT[(d4 + 0) * TST + t] = q4.x;
        sQT[(d4 + 1) * TST + t] = q4.y;
        sQT[(d4 + 2) * TST + t] = q4.z;
        sQT[(d4 + 3) * TST + t] = q4.w;
        sKT[(d4 + 0) * TST + t] = k4.x;
        sKT[(d4 + 1) * TST + t] = k4.y;
        sKT[(d4 + 2) * TST + t] = k4.z;
        sKT[(d4 + 3) * TST + t] = k4.w;
    }
    {
        const float* rg = Rg + (size_t)((b * NJ + n) * NH + h) * TT * 36;
        for (int i = tid; i < (TT * 36) / 4; i += 256)
            reinterpret_cast<float4*>(sR)[i] =
                reinterpret_cast<const float4*>(rg)[i];
    }
    for (int i = tid; i < (33 * 32) / 4; i += 256)
        reinterpret_cast<float4*>(srv)[i] =
            reinterpret_cast<const float4*>(relv)[i];
    __syncthreads();

    const float scale = 0.17677669529663687f;  // 1/sqrt(32)
    for (int p = tid; p < 465; p += 256) {
        int ti = (int)((sqrtf(8.f * (float)p + 1.f) - 1.f) * 0.5f);
        while ((ti + 1) * (ti + 2) / 2 <= p) ti++;
        while (ti * (ti + 1) / 2 > p) ti--;
        const int si = p - ti * (ti + 1) / 2;
        const int tt = ti * 4, ss = si * 4;

        float c[4][4];
#pragma unroll
        for (int i = 0; i < 4; i++)
#pragma unroll
            for (int j = 0; j < 4; j++) c[i][j] = 0.f;

#pragma unroll
        for (int d = 0; d < 32; d++) {
            const float4 a = *reinterpret_cast<const float4*>(&sQT[d * TST + tt]);
            const float4 k4 = *reinterpret_cast<const float4*>(&sKT[d * TST + ss]);
            c[0][0] = fmaf(a.x, k4.x, c[0][0]); c[0][1] = fmaf(a.x, k4.y, c[0][1]);
            c[0][2] = fmaf(a.x, k4.z, c[0][2]); c[0][3] = fmaf(a.x, k4.w, c[0][3]);
            c[1][0] = fmaf(a.y, k4.x, c[1][0]); c[1][1] = fmaf(a.y, k4.y, c[1][1]);
            c[1][2] = fmaf(a.y, k4.z, c[1][2]); c[1][3] = fmaf(a.y, k4.w, c[1][3]);
            c[2][0] = fmaf(a.z, k4.x, c[2][0]); c[2][1] = fmaf(a.z, k4.y, c[2][1]);
            c[2][2] = fmaf(a.z, k4.z, c[2][2]); c[2][3] = fmaf(a.z, k4.w, c[2][3]);
            c[3][0] = fmaf(a.w, k4.x, c[3][0]); c[3][1] = fmaf(a.w, k4.y, c[3][1]);
            c[3][2] = fmaf(a.w, k4.z, c[3][2]); c[3][3] = fmaf(a.w, k4.w, c[3][3]);
        }

#pragma unroll
        for (int i = 0; i < 4; i++) {
            const int t = tt + i;
            const int o = SOFF(t);
#pragma unroll
            for (int j = 0; j < 4; j++) {
                const int s = ss + j;
                if (s <= t) {
                    int idx = s - t + 32;
                    idx = idx < 0 ? 0 : idx;
                    sS[o + s] = (c[i][j] + sR[t * VST + idx]) * scale;
                }
            }
        }
    }
    __syncthreads();

    {
        const int wid = tid >> 5, lane = tid & 31;
        for (int t = wid; t < TT; t += 8) {
            float* row = sS + SOFF(t);
            float m = -1e30f;
            for (int s = lane; s <= t; s += 32) m = fmaxf(m, row[s]);
#pragma unroll
            for (int o = 16; o > 0; o >>= 1)
                m = fmaxf(m, __shfl_xor_sync(0xffffffffu, m, o));
            float sum = 0.f;
            for (int s = lane; s <= t; s += 32) {
                const float e = __expf(row[s] - m);
                row[s] = e;
                sum += e;
            }
#pragma unroll
            for (int o = 16; o > 0; o >>= 1)
                sum += __shfl_xor_sync(0xffffffffu, sum, o);
            const float inv = 1.f / sum;
            float a0 = 0.f;
            for (int s = lane; s <= t; s += 32) {
                const float a = row[s] * inv;
                row[s] = a;
                if (s <= t - 32) a0 += a;
            }
#pragma unroll
            for (int o = 16; o > 0; o >>= 1)
                a0 += __shfl_xor_sync(0xffffffffu, a0, o);
            if (lane == 0) sA0[t] = a0;
        }
    }
    __syncthreads();

    for (int p = tid; p < 240; p += 256) {
        const int tt = (p / 8) * 4, dd = (p % 8) * 4;
        const int o0 = SOFF(tt + 0), o1 = SOFF(tt + 1);
        const int o2 = SOFF(tt + 2), o3 = SOFF(tt + 3);

        float4 c0 = {0.f, 0.f, 0.f, 0.f}, c1 = c0, c2 = c0, c3 = c0;

#pragma unroll 2
        for (int s = 0; s < tt; s++) {
            const float a0 = sS[o0 + s];
            const float a1 = sS[o1 + s];
            const float a2 = sS[o2 + s];
            const float a3 = sS[o3 + s];
            const float4 v = *reinterpret_cast<const float4*>(&sv[s * VST + dd]);
            c0.x = fmaf(a0, v.x, c0.x); c0.y = fmaf(a0, v.y, c0.y);
            c0.z = fmaf(a0, v.z, c0.z); c0.w = fmaf(a0, v.w, c0.w);
            c1.x = fmaf(a1, v.x, c1.x); c1.y = fmaf(a1, v.y, c1.y);
            c1.z = fmaf(a1, v.z, c1.z); c1.w = fmaf(a1, v.w, c1.w);
            c2.x = fmaf(a2, v.x, c2.x); c2.y = fmaf(a2, v.y, c2.y);
            c2.z = fmaf(a2, v.z, c2.z); c2.w = fmaf(a2, v.w, c2.w);
            c3.x = fmaf(a3, v.x, c3.x); c3.y = fmaf(a3, v.y, c3.y);
            c3.z = fmaf(a3, v.z, c3.z); c3.w = fmaf(a3, v.w, c3.w);
        }
        float4* cc[4] = {&c0, &c1, &c2, &c3};
        const int oo[4] = {o0, o1, o2, o3};
#pragma unroll
        for (int j = 0; j < 4; j++) {
            const int s = tt + j;
            const float4 v = *reinterpret_cast<const float4*>(&sv[s * VST + dd]);
#pragma unroll
            for (int i = 0; i < 4; i++) {
                if (j <= i) {
                    const float a = sS[oo[i] + s];
                    cc[i]->x = fmaf(a, v.x, cc[i]->x);
                    cc[i]->y = fmaf(a, v.y, cc[i]->y);
                    cc[i]->z = fmaf(a, v.z, cc[i]->z);
                    cc[i]->w = fmaf(a, v.w, cc[i]->w);
                }
            }
        }

        {
            const float4 r0 = *reinterpret_cast<const float4*>(&srv[dd]);
#pragma unroll
            for (int i = 0; i < 4; i++) {
                const float a0v = sA0[tt + i];
                cc[i]->x = fmaf(a0v, r0.x, cc[i]->x);
                cc[i]->y = fmaf(a0v, r0.y, cc[i]->y);
                cc[i]->z = fmaf(a0v, r0.z, cc[i]->z);
                cc[i]->w = fmaf(a0v, r0.w, cc[i]->w);
            }
        }
        const int slo = (tt - 31) > 0 ? (tt - 31) : 0;
        for (int s = slo; s <= tt + 3; s++) {
#pragma unroll
            for (int i = 0; i < 4; i++) {
                const int idx = s - (tt + i) + 32;
                if (idx >= 1 && idx <= 32) {
                    const float a = sS[oo[i] + s];
                    const float4 r = *reinterpret_cast<const float4*>(
                        &srv[idx * 32 + dd]);
                    cc[i]->x = fmaf(a, r.x, cc[i]->x);
                    cc[i]->y = fmaf(a, r.y, cc[i]->y);
                    cc[i]->z = fmaf(a, r.z, cc[i]->z);
                    cc[i]->w = fmaf(a, r.w, cc[i]->w);
                }
            }
        }

#pragma unroll
        for (int i = 0; i < 4; i++) {
            const size_t g = base + (size_t)(tt + i) * (NJ * DIM) + dd;
            *reinterpret_cast<float4*>(&O[g]) = *cc[i];
        }
    }
}

// ---------------------------------------------------------------------------
// Spatial attention: one block per (b,t); all 8 heads over N=24 joints.
// ---------------------------------------------------------------------------
#define SATTN_SMEM (23040 * 4)

__global__ void __launch_bounds__(256) sattn(
    const float* __restrict__ Q, const float* __restrict__ K,
    const float* __restrict__ V, float* __restrict__ O)
{
    extern __shared__ float sm[];
    float* sq = sm;            // [24][256]
    float* sk = sq + 6144;
    float* sv = sk + 6144;
    float* sS = sv + 6144;     // [8][24][24]

    const int tid = threadIdx.x;
    const size_t base = (size_t)blockIdx.x * (NJ * DIM);

    for (int i = tid; i < NJ * DIM; i += 256) {
        sq[i] = Q[base + i];
        sk[i] = K[base + i];
        sv[i] = V[base + i];
    }
    __syncthreads();

    const float scale = 0.17677669529663687f;
    for (int p = tid; p < NH * NJ * NJ; p += 256) {
        const int hh = p / (NJ * NJ);
        const int r = p % (NJ * NJ);
        const int i = r / NJ, j = r % NJ;
        const float* qa = sq + i * DIM + hh * DPH;
        const float* ka = sk + j * DIM + hh * DPH;
        float s = 0.f;
#pragma unroll
        for (int d = 0; d < 32; d++) s = fmaf(qa[d], ka[d], s);
        sS[p] = s * scale;
    }
    __syncthreads();

    for (int r = tid; r < NH * NJ; r += 256) {
        float* row = sS + r * NJ;
        float m = -1e30f;
#pragma unroll
        for (int j = 0; j < NJ; j++) m = fmaxf(m, row[j]);
        float sum = 0.f;
#pragma unroll
        for (int j = 0; j < NJ; j++) {
            const float e = __expf(row[j] - m);
            row[j] = e;
            sum += e;
        }
        const float inv = 1.f / sum;
#pragma unroll
        for (int j = 0; j < NJ; j++) row[j] *= inv;
    }
    __syncthreads();

    for (int p = tid; p < NJ * DIM; p += 256) {
        const int hh = p / (NJ * DPH);
        const int r = p % (NJ * DPH);
        const int i = r / DPH, d = r % DPH;
        const float* arow = sS + hh * (NJ * NJ) + i * NJ;
        const float* vcol = sv + hh * DPH + d;
        float s = 0.f;
#pragma unroll
        for (int j = 0; j < NJ; j++) s = fmaf(arow[j], vcol[j * DIM], s);
        O[base + (size_t)i * DIM + hh * DPH + d] = s;
    }
}

// ---------------------------------------------------------------------------
// launch
// ---------------------------------------------------------------------------
extern "C" void kernel_launch(void* const* d_in, const int* in_sizes, int n_in,
                              void* d_out, int out_size)
{
    (void)in_sizes; (void)n_in; (void)out_size;
    const float* x    = (const float*)d_in[0];
    // d_in[1] = mask: exactly triu(1) -> handled analytically (exp underflow)
    const float* wq_t = (const float*)d_in[2];
    const float* wk_t = (const float*)d_in[3];
    const float* wv_t = (const float*)d_in[4];
    const float* bq_t = (const float*)d_in[5];
    const float* bk_t = (const float*)d_in[6];
    const float* bv_t = (const float*)d_in[7];
    const float* wo_t = (const float*)d_in[8];
    const float* bo_t = (const float*)d_in[9];
    const float* relk = (const float*)d_in[10];
    const float* relv = (const float*)d_in[11];
    const float* wq_s = (const float*)d_in[12];
    const float* wk_s = (const float*)d_in[13];
    const float* wv_s = (const float*)d_in[14];
    const float* wo_s = (const float*)d_in[15];
    const float* bq_s = (const float*)d_in[16];
    const float* bk_s = (const float*)d_in[17];
    const float* bv_s = (const float*)d_in[18];
    const float* bo_s = (const float*)d_in[19];
    const float* ff1w = (const float*)d_in[20];
    const float* ff1b = (const float*)d_in[21];
    const float* ff2w = (const float*)d_in[22];
    const float* ff2b = (const float*)d_in[23];
    float* out = (float*)d_out;

    float *dq, *dk, *dv, *dao, *dy, *dh, *dr;
    cudaGetSymbolAddress((void**)&dq, g_q);
    cudaGetSymbolAddress((void**)&dk, g_k);
    cudaGetSymbolAddress((void**)&dv, g_v);
    cudaGetSymbolAddress((void**)&dao, g_ao);
    cudaGetSymbolAddress((void**)&dy, g_y);
    cudaGetSymbolAddress((void**)&dh, g_h);
    cudaGetSymbolAddress((void**)&dr, g_r);

    cudaFuncSetAttribute(tattn, cudaFuncAttributeMaxDynamicSharedMemorySize,
                         TATTN_SMEM);
    cudaFuncSetAttribute(sattn, cudaFuncAttributeMaxDynamicSharedMemorySize,
                         SATTN_SMEM);

    const dim3 gj(BT / 128, DIM / 128, NJ);        // per-joint single GEMM
    const dim3 gj3(BT / 128, DIM / 128, 3 * NJ);   // fused per-joint QKV
    const dim3 gs(ROWS / 128, DIM / 128, 1);       // shared-weight single GEMM
    const dim3 gs3(ROWS / 128, DIM / 128, 3);      // fused shared QKV
    const dim3 gbnh(NH, NJ, BB);

    // ---- temporal attention path (fused per-joint QKV) ----
    gemm128_qkv<<<gj3, 256>>>(x, wq_t, wk_t, wv_t, bq_t, bk_t, bv_t,
                              dq, dk, dv, NJ * DIM, DIM, DIM * DIM, DIM, NJ);
    rproj<<<gbnh, 128>>>(dq, relk, dr);
    tattn<<<gbnh, 256, TATTN_SMEM>>>(dq, dk, dv, dr, relv, dao);
    // y = x + t_out
    gemm128<<<gs, 256>>>(dao, wo_t, bo_t, x, dy, DIM, 0, 0, 0, 0);

    // ---- spatial attention path (fused shared QKV; input is x, not y) ----
    gemm128_qkv<<<gs3, 256>>>(x, wq_s, wk_s, wv_s, bq_s, bk_s, bv_s,
                              dq, dk, dv, DIM, 0, 0, 0, 1);
    sattn<<<BT, 256, SATTN_SMEM>>>(dq, dk, dv, dao);
    // y += s_out
    gemm128<<<gs, 256>>>(dao, wo_s, bo_s, dy, dy, DIM, 0, 0, 0, 0);

    // ---- per-joint FFN + residual ----
    gemm128<<<gj, 256>>>(dy, ff1w, ff1b, nullptr, dh, NJ * DIM, DIM, DIM * DIM, DIM, 1);
    gemm128<<<gj, 256>>>(dh, ff2w, ff2b, dy, out, NJ * DIM, DIM, DIM * DIM, DIM, 0);
}